// round 1
// baseline (speedup 1.0000x reference)
#include <cuda_runtime.h>
#include <math.h>

#define BATCH  2
#define SLEN   2048
#define DMODEL 1024
#define HEADS  16
#define DHEAD  64
#define MTOT   (BATCH * SLEN)   // 4096

// ---------------- scratch (device globals; no allocation allowed) ----------
__device__ float g_q[MTOT * DMODEL];
__device__ float g_k[MTOT * DMODEL];
__device__ float g_v[MTOT * DMODEL];
__device__ float g_ctx[MTOT * DMODEL];

// ---------------------------------------------------------------------------
// 128x128x8 fp32 SGEMM, 256 threads, 8x8 per-thread microtile.
// C[M,N] = A[M,K] @ B[K,N] * scale (+ bias[n] if bias != nullptr)
// M,N,K all multiples of 128/128/8 here (4096,1024,1024) -> no bounds checks.
// ---------------------------------------------------------------------------
__global__ __launch_bounds__(256) void sgemm_kernel(
    const float* __restrict__ A, const float* __restrict__ B,
    float* __restrict__ C, int M, int N, int K,
    float scale, const float* __restrict__ bias)
{
    __shared__ float As[8][128];   // A tile, transposed: As[k][m]
    __shared__ float Bs[8][128];   // B tile: Bs[k][n]

    const int t  = threadIdx.x;
    const int tx = t & 15;
    const int ty = t >> 4;
    const int m0 = blockIdx.y * 128;
    const int n0 = blockIdx.x * 128;

    const int arow = t >> 1;          // 0..127
    const int acol = (t & 1) << 2;    // 0 or 4
    const int brow = t >> 5;          // 0..7
    const int bcol = (t & 31) << 2;   // 0..124

    const float* Ap = A + (size_t)(m0 + arow) * K + acol;
    const float* Bp = B + (size_t)brow * N + n0 + bcol;

    float acc[8][8];
#pragma unroll
    for (int i = 0; i < 8; i++)
#pragma unroll
        for (int j = 0; j < 8; j++) acc[i][j] = 0.f;

    for (int kt = 0; kt < K; kt += 8) {
        float4 av = *(const float4*)(Ap + kt);
        float4 bv = *(const float4*)(Bp + (size_t)kt * N);
        As[acol + 0][arow] = av.x;
        As[acol + 1][arow] = av.y;
        As[acol + 2][arow] = av.z;
        As[acol + 3][arow] = av.w;
        *(float4*)(&Bs[brow][bcol]) = bv;
        __syncthreads();

#pragma unroll
        for (int k = 0; k < 8; k++) {
            float a[8], b[8];
            float4 t0 = *(const float4*)(&As[k][ty << 2]);
            float4 t1 = *(const float4*)(&As[k][64 + (ty << 2)]);
            float4 t2 = *(const float4*)(&Bs[k][tx << 2]);
            float4 t3 = *(const float4*)(&Bs[k][64 + (tx << 2)]);
            a[0] = t0.x; a[1] = t0.y; a[2] = t0.z; a[3] = t0.w;
            a[4] = t1.x; a[5] = t1.y; a[6] = t1.z; a[7] = t1.w;
            b[0] = t2.x; b[1] = t2.y; b[2] = t2.z; b[3] = t2.w;
            b[4] = t3.x; b[5] = t3.y; b[6] = t3.z; b[7] = t3.w;
#pragma unroll
            for (int i = 0; i < 8; i++)
#pragma unroll
                for (int j = 0; j < 8; j++)
                    acc[i][j] += a[i] * b[j];
        }
        __syncthreads();
    }

#pragma unroll
    for (int i = 0; i < 8; i++) {
        int rr = (i < 4) ? ((ty << 2) + i) : (64 + (ty << 2) + i - 4);
        float* Cp = C + (size_t)(m0 + rr) * N + n0;
#pragma unroll
        for (int j = 0; j < 8; j++) {
            int cc = (j < 4) ? ((tx << 2) + j) : (64 + (tx << 2) + j - 4);
            float v = acc[i][j] * scale;
            if (bias) v += bias[n0 + cc];
            Cp[cc] = v;
        }
    }
}

// ---------------------------------------------------------------------------
// Causal flash attention, fp32. Grid: (S/64, HEADS, BATCH), 256 threads.
// BQ = BK = 64, Dh = 64. Online softmax. P staged in shared memory.
// Shared (dynamic): Qs/Ks/Vs/Ps each 64 x 68 floats (pitch 68 -> bank spread,
// 68*4 = 272 B row pitch is 16B aligned so float4 works). Total 69632 B.
// Score scale (1/sqrt(64)) is pre-folded into g_q by the Q projection.
// ---------------------------------------------------------------------------
#define ATTN_PITCH 68
#define ATTN_SMEM  (4 * 64 * ATTN_PITCH * (int)sizeof(float))

__device__ __forceinline__ float warp16_max(float v) {
#pragma unroll
    for (int off = 8; off > 0; off >>= 1)
        v = fmaxf(v, __shfl_xor_sync(0xffffffffu, v, off));
    return v;
}
__device__ __forceinline__ float warp16_sum(float v) {
#pragma unroll
    for (int off = 8; off > 0; off >>= 1)
        v += __shfl_xor_sync(0xffffffffu, v, off);
    return v;
}

__global__ __launch_bounds__(256) void attn_kernel()
{
    extern __shared__ float sm[];
    float* Qs = sm;
    float* Ks = sm + 64 * ATTN_PITCH;
    float* Vs = sm + 2 * 64 * ATTN_PITCH;
    float* Ps = sm + 3 * 64 * ATTN_PITCH;

    const int qt = blockIdx.x;
    const int h  = blockIdx.y;
    const int b  = blockIdx.z;
    const int t  = threadIdx.x;
    const int tx = t & 15;
    const int ty = t >> 4;

    const float* Qg = g_q + (size_t)b * SLEN * DMODEL + h * DHEAD;
    const float* Kg = g_k + (size_t)b * SLEN * DMODEL + h * DHEAD;
    const float* Vg = g_v + (size_t)b * SLEN * DMODEL + h * DHEAD;

    // load Q tile (64 rows x 64 cols) into shared
#pragma unroll
    for (int i = 0; i < 4; i++) {
        int idx = t + 256 * i;          // 0..1023 -> 64 rows x 16 float4
        int r   = idx >> 4;
        int c   = (idx & 15) << 2;
        *(float4*)(Qs + r * ATTN_PITCH + c) =
            *(const float4*)(Qg + (size_t)(qt * 64 + r) * DMODEL + c);
    }

    float m_i[4], l_i[4], O[4][4];
#pragma unroll
    for (int i = 0; i < 4; i++) {
        m_i[i] = -1e30f;
        l_i[i] = 0.f;
#pragma unroll
        for (int j = 0; j < 4; j++) O[i][j] = 0.f;
    }

    for (int kt = 0; kt <= qt; kt++) {
        __syncthreads();  // prev-iter PV done (and Q load visible via next sync)
        // load K, V tiles
#pragma unroll
        for (int i = 0; i < 4; i++) {
            int idx = t + 256 * i;
            int r   = idx >> 4;
            int c   = (idx & 15) << 2;
            size_t g = (size_t)(kt * 64 + r) * DMODEL + c;
            *(float4*)(Ks + r * ATTN_PITCH + c) = *(const float4*)(Kg + g);
            *(float4*)(Vs + r * ATTN_PITCH + c) = *(const float4*)(Vg + g);
        }
        __syncthreads();

        // scores: s[i][j] = Q[ty*4+i] . K[tx*4+j]  over d=0..63
        float s[4][4];
#pragma unroll
        for (int i = 0; i < 4; i++)
#pragma unroll
            for (int j = 0; j < 4; j++) s[i][j] = 0.f;

        for (int d = 0; d < DHEAD; d += 4) {
            float qa[4][4], kb[4][4];
#pragma unroll
            for (int i = 0; i < 4; i++) {
                float4 v = *(const float4*)(Qs + ((ty << 2) + i) * ATTN_PITCH + d);
                qa[i][0] = v.x; qa[i][1] = v.y; qa[i][2] = v.z; qa[i][3] = v.w;
            }
#pragma unroll
            for (int j = 0; j < 4; j++) {
                float4 v = *(const float4*)(Ks + ((tx << 2) + j) * ATTN_PITCH + d);
                kb[j][0] = v.x; kb[j][1] = v.y; kb[j][2] = v.z; kb[j][3] = v.w;
            }
#pragma unroll
            for (int i = 0; i < 4; i++)
#pragma unroll
                for (int j = 0; j < 4; j++)
#pragma unroll
                    for (int dd = 0; dd < 4; dd++)
                        s[i][j] += qa[i][dd] * kb[j][dd];
        }

        // causal mask on the diagonal tile
        if (kt == qt) {
#pragma unroll
            for (int i = 0; i < 4; i++)
#pragma unroll
                for (int j = 0; j < 4; j++)
                    if (((tx << 2) + j) > ((ty << 2) + i)) s[i][j] = -1e30f;
        }

        // online softmax update + stage P
#pragma unroll
        for (int i = 0; i < 4; i++) {
            float rm = fmaxf(fmaxf(s[i][0], s[i][1]), fmaxf(s[i][2], s[i][3]));
            rm = warp16_max(rm);
            float m_new = fmaxf(m_i[i], rm);
            float alpha = __expf(m_i[i] - m_new);
            float p[4], rs = 0.f;
#pragma unroll
            for (int j = 0; j < 4; j++) {
                p[j] = __expf(s[i][j] - m_new);
                rs  += p[j];
            }
            rs = warp16_sum(rs);
            l_i[i] = l_i[i] * alpha + rs;
            m_i[i] = m_new;
#pragma unroll
            for (int j = 0; j < 4; j++) {
                O[i][j] *= alpha;
                Ps[((ty << 2) + i) * ATTN_PITCH + (tx << 2) + j] = p[j];
            }
        }
        __syncthreads();

        // O += P @ V   (k = 0..63)
        for (int k0 = 0; k0 < 64; k0 += 4) {
            float pa[4][4], vb[4][4];
#pragma unroll
            for (int i = 0; i < 4; i++) {
                float4 v = *(const float4*)(Ps + ((ty << 2) + i) * ATTN_PITCH + k0);
                pa[i][0] = v.x; pa[i][1] = v.y; pa[i][2] = v.z; pa[i][3] = v.w;
            }
#pragma unroll
            for (int kk = 0; kk < 4; kk++) {
                float4 v = *(const float4*)(Vs + (k0 + kk) * ATTN_PITCH + (tx << 2));
                vb[kk][0] = v.x; vb[kk][1] = v.y; vb[kk][2] = v.z; vb[kk][3] = v.w;
            }
#pragma unroll
            for (int i = 0; i < 4; i++)
#pragma unroll
                for (int kk = 0; kk < 4; kk++)
#pragma unroll
                    for (int j = 0; j < 4; j++)
                        O[i][j] += pa[i][kk] * vb[kk][j];
        }
    }

    // finalize and write context
#pragma unroll
    for (int i = 0; i < 4; i++) {
        float inv = 1.f / l_i[i];
        float4 o4;
        o4.x = O[i][0] * inv; o4.y = O[i][1] * inv;
        o4.z = O[i][2] * inv; o4.w = O[i][3] * inv;
        int r = qt * 64 + (ty << 2) + i;
        *(float4*)(g_ctx + (size_t)(b * SLEN + r) * DMODEL + h * DHEAD + (tx << 2)) = o4;
    }
}

// ---------------------------------------------------------------------------
extern "C" void kernel_launch(void* const* d_in, const int* in_sizes, int n_in,
                              void* d_out, int out_size)
{
    const float* x  = (const float*)d_in[0];
    const float* wq = (const float*)d_in[1];
    const float* wk = (const float*)d_in[2];
    const float* wv = (const float*)d_in[3];
    const float* wo = (const float*)d_in[4];
    const float* bo = (const float*)d_in[5];
    float* out = (float*)d_out;

    void *pq, *pk, *pv, *pctx;
    cudaGetSymbolAddress(&pq,   g_q);
    cudaGetSymbolAddress(&pk,   g_k);
    cudaGetSymbolAddress(&pv,   g_v);
    cudaGetSymbolAddress(&pctx, g_ctx);

    cudaFuncSetAttribute(attn_kernel,
                         cudaFuncAttributeMaxDynamicSharedMemorySize, ATTN_SMEM);

    dim3 gblk(256);
    dim3 ggrid(DMODEL / 128, MTOT / 128);   // (8, 32)

    // QKV projections; score scale folded into Q (1/sqrt(64) = 0.125)
    sgemm_kernel<<<ggrid, gblk>>>(x, wq, (float*)pq, MTOT, DMODEL, DMODEL,
                                  0.125f, nullptr);
    sgemm_kernel<<<ggrid, gblk>>>(x, wk, (float*)pk, MTOT, DMODEL, DMODEL,
                                  1.0f, nullptr);
    sgemm_kernel<<<ggrid, gblk>>>(x, wv, (float*)pv, MTOT, DMODEL, DMODEL,
                                  1.0f, nullptr);

    // causal flash attention
    dim3 agrid(SLEN / 64, HEADS, BATCH);    // (32, 16, 2)
    attn_kernel<<<agrid, 256, ATTN_SMEM>>>();

    // output projection + bias
    sgemm_kernel<<<ggrid, gblk>>>((const float*)pctx, wo, out, MTOT, DMODEL,
                                  DMODEL, 1.0f, bo);
}

// round 3
// speedup vs baseline: 1.2510x; 1.2510x over previous
#include <cuda_runtime.h>
#include <math.h>
#include <stdint.h>

#define BATCH  2
#define SLEN   2048
#define DMODEL 1024
#define HEADS  16
#define DHEAD  64
#define MTOT   (BATCH * SLEN)   // 4096

// ---------------- scratch (device globals; no allocation allowed) ----------
__device__ float g_q[MTOT * DMODEL];
__device__ float g_k[MTOT * DMODEL];
__device__ float g_v[MTOT * DMODEL];
__device__ float g_ctx[MTOT * DMODEL];

// ===========================================================================
// tf32 tensor-core GEMM: C[M,N] = A[M,K] @ B[K,N] * scale (+ bias[n])
// Tile: 128x128x32. 256 threads = 8 warps as 4(M) x 2(N) -> warp tile 32x64.
// mma.sync.aligned.m16n8k8.row.col.f32.tf32.tf32.f32
// Inputs converted to tf32 (cvt.rna -> b32 reg) during staging.
// ===========================================================================
#define GA_PITCH 36    // A smem row pitch (128 rows x 32 cols)
#define GB_PITCH 132   // B smem row pitch (32 rows x 128 cols)
#define GA_SIZE  (128 * GA_PITCH)          // 4608 floats
#define GB_SIZE  (32 * GB_PITCH)           // 4224 floats
#define GEMM_SMEM ((GA_SIZE + GB_SIZE) * 2 * (int)sizeof(float))  // 70656 B

__device__ __forceinline__ uint32_t to_tf32(float x) {
    uint32_t r;
    asm("cvt.rna.tf32.f32 %0, %1;" : "=r"(r) : "f"(x));
    return r;
}

__device__ __forceinline__ void mma_tf32(float c[4], const uint32_t a[4],
                                         const uint32_t b[2]) {
    asm volatile(
        "mma.sync.aligned.m16n8k8.row.col.f32.tf32.tf32.f32 "
        "{%0,%1,%2,%3}, {%4,%5,%6,%7}, {%8,%9}, {%0,%1,%2,%3};"
        : "+f"(c[0]), "+f"(c[1]), "+f"(c[2]), "+f"(c[3])
        : "r"(a[0]), "r"(a[1]), "r"(a[2]), "r"(a[3]), "r"(b[0]), "r"(b[1]));
}

__device__ __forceinline__ float4 cvt4(float4 v) {
    float4 o;
    o.x = __uint_as_float(to_tf32(v.x));
    o.y = __uint_as_float(to_tf32(v.y));
    o.z = __uint_as_float(to_tf32(v.z));
    o.w = __uint_as_float(to_tf32(v.w));
    return o;
}

__global__ __launch_bounds__(256) void tf32_gemm_kernel(
    const float* __restrict__ A, const float* __restrict__ B,
    float* __restrict__ C, int M, int N, int K,
    float scale, const float* __restrict__ bias)
{
    extern __shared__ float sm[];
    float* AsBuf[2] = { sm, sm + GA_SIZE + GB_SIZE };
    float* BsBuf[2] = { sm + GA_SIZE, sm + 2 * GA_SIZE + GB_SIZE };

    const int t    = threadIdx.x;
    const int lane = t & 31;
    const int warp = t >> 5;
    const int m0   = blockIdx.y * 128;
    const int n0   = blockIdx.x * 128;
    const int wm   = (warp & 3) * 32;   // warp M offset in tile
    const int wn   = (warp >> 2) * 64;  // warp N offset in tile

    const int ar = t >> 3;          // A row base (advances +32 per i)
    const int ac = (t & 7) << 2;    // A col (0..28)
    const int br = t >> 5;          // B row base (advances +8 per i)
    const int bc = (t & 31) << 2;   // B col (0..124)

    const float* Ag = A + (size_t)m0 * K;
    const float* Bg = B + n0;

    float acc[2][8][4];
#pragma unroll
    for (int mi = 0; mi < 2; mi++)
#pragma unroll
        for (int ni = 0; ni < 8; ni++)
#pragma unroll
            for (int r = 0; r < 4; r++) acc[mi][ni][r] = 0.f;

    float4 aR[4], bR[4];
    const int nt = K / 32;

    // prefetch tile 0
#pragma unroll
    for (int i = 0; i < 4; i++) {
        aR[i] = *(const float4*)(Ag + (size_t)(ar + i * 32) * K + ac);
        bR[i] = *(const float4*)(Bg + (size_t)(br + i * 8) * N + bc);
    }
#pragma unroll
    for (int i = 0; i < 4; i++) {
        *(float4*)(&AsBuf[0][(ar + i * 32) * GA_PITCH + ac]) = cvt4(aR[i]);
        *(float4*)(&BsBuf[0][(br + i * 8) * GB_PITCH + bc]) = cvt4(bR[i]);
    }
    __syncthreads();

    int cur = 0;
    for (int kt = 0; kt < nt; kt++) {
        if (kt + 1 < nt) {
            const int k0n = (kt + 1) * 32;
#pragma unroll
            for (int i = 0; i < 4; i++) {
                aR[i] = *(const float4*)(Ag + (size_t)(ar + i * 32) * K + k0n + ac);
                bR[i] = *(const float4*)(Bg + (size_t)(k0n + br + i * 8) * N + bc);
            }
        }

        const float* As = AsBuf[cur];
        const float* Bs = BsBuf[cur];
#pragma unroll
        for (int ks = 0; ks < 4; ks++) {
            const int k0 = ks * 8;
            uint32_t afr[2][4], bfr[8][2];
#pragma unroll
            for (int mi = 0; mi < 2; mi++) {
                int base = (wm + mi * 16 + (lane >> 2)) * GA_PITCH + k0 + (lane & 3);
                afr[mi][0] = __float_as_uint(As[base]);
                afr[mi][1] = __float_as_uint(As[base + 8 * GA_PITCH]);
                afr[mi][2] = __float_as_uint(As[base + 4]);
                afr[mi][3] = __float_as_uint(As[base + 8 * GA_PITCH + 4]);
            }
#pragma unroll
            for (int ni = 0; ni < 8; ni++) {
                int base = (k0 + (lane & 3)) * GB_PITCH + wn + ni * 8 + (lane >> 2);
                bfr[ni][0] = __float_as_uint(Bs[base]);
                bfr[ni][1] = __float_as_uint(Bs[base + 4 * GB_PITCH]);
            }
#pragma unroll
            for (int mi = 0; mi < 2; mi++)
#pragma unroll
                for (int ni = 0; ni < 8; ni++)
                    mma_tf32(acc[mi][ni], afr[mi], bfr[ni]);
        }

        if (kt + 1 < nt) {
            float* An = AsBuf[cur ^ 1];
            float* Bn = BsBuf[cur ^ 1];
#pragma unroll
            for (int i = 0; i < 4; i++) {
                *(float4*)(&An[(ar + i * 32) * GA_PITCH + ac]) = cvt4(aR[i]);
                *(float4*)(&Bn[(br + i * 8) * GB_PITCH + bc]) = cvt4(bR[i]);
            }
        }
        __syncthreads();
        cur ^= 1;
    }

    // epilogue
#pragma unroll
    for (int mi = 0; mi < 2; mi++) {
        const int row0 = m0 + wm + mi * 16 + (lane >> 2);
#pragma unroll
        for (int ni = 0; ni < 8; ni++) {
            const int col = n0 + wn + ni * 8 + ((lane & 3) << 1);
            float b0 = 0.f, b1 = 0.f;
            if (bias) { b0 = bias[col]; b1 = bias[col + 1]; }
            float2 v0, v1;
            v0.x = acc[mi][ni][0] * scale + b0;
            v0.y = acc[mi][ni][1] * scale + b1;
            v1.x = acc[mi][ni][2] * scale + b0;
            v1.y = acc[mi][ni][3] * scale + b1;
            *(float2*)(C + (size_t)row0 * N + col) = v0;
            *(float2*)(C + (size_t)(row0 + 8) * N + col) = v1;
        }
    }
}

// ---------------------------------------------------------------------------
// Causal flash attention, fp32 (unchanged).
// ---------------------------------------------------------------------------
#define ATTN_PITCH 68
#define ATTN_SMEM  (4 * 64 * ATTN_PITCH * (int)sizeof(float))

__device__ __forceinline__ float warp16_max(float v) {
#pragma unroll
    for (int off = 8; off > 0; off >>= 1)
        v = fmaxf(v, __shfl_xor_sync(0xffffffffu, v, off));
    return v;
}
__device__ __forceinline__ float warp16_sum(float v) {
#pragma unroll
    for (int off = 8; off > 0; off >>= 1)
        v += __shfl_xor_sync(0xffffffffu, v, off);
    return v;
}

__global__ __launch_bounds__(256) void attn_kernel()
{
    extern __shared__ float smf[];
    float* Qs = smf;
    float* Ks = smf + 64 * ATTN_PITCH;
    float* Vs = smf + 2 * 64 * ATTN_PITCH;
    float* Ps = smf + 3 * 64 * ATTN_PITCH;

    const int qt = blockIdx.x;
    const int h  = blockIdx.y;
    const int b  = blockIdx.z;
    const int t  = threadIdx.x;
    const int tx = t & 15;
    const int ty = t >> 4;

    const float* Qg = g_q + (size_t)b * SLEN * DMODEL + h * DHEAD;
    const float* Kg = g_k + (size_t)b * SLEN * DMODEL + h * DHEAD;
    const float* Vg = g_v + (size_t)b * SLEN * DMODEL + h * DHEAD;

#pragma unroll
    for (int i = 0; i < 4; i++) {
        int idx = t + 256 * i;
        int r   = idx >> 4;
        int c   = (idx & 15) << 2;
        *(float4*)(Qs + r * ATTN_PITCH + c) =
            *(const float4*)(Qg + (size_t)(qt * 64 + r) * DMODEL + c);
    }

    float m_i[4], l_i[4], O[4][4];
#pragma unroll
    for (int i = 0; i < 4; i++) {
        m_i[i] = -1e30f;
        l_i[i] = 0.f;
#pragma unroll
        for (int j = 0; j < 4; j++) O[i][j] = 0.f;
    }

    for (int kt = 0; kt <= qt; kt++) {
        __syncthreads();
#pragma unroll
        for (int i = 0; i < 4; i++) {
            int idx = t + 256 * i;
            int r   = idx >> 4;
            int c   = (idx & 15) << 2;
            size_t g = (size_t)(kt * 64 + r) * DMODEL + c;
            *(float4*)(Ks + r * ATTN_PITCH + c) = *(const float4*)(Kg + g);
            *(float4*)(Vs + r * ATTN_PITCH + c) = *(const float4*)(Vg + g);
        }
        __syncthreads();

        float s[4][4];
#pragma unroll
        for (int i = 0; i < 4; i++)
#pragma unroll
            for (int j = 0; j < 4; j++) s[i][j] = 0.f;

        for (int d = 0; d < DHEAD; d += 4) {
            float qa[4][4], kb[4][4];
#pragma unroll
            for (int i = 0; i < 4; i++) {
                float4 v = *(const float4*)(Qs + ((ty << 2) + i) * ATTN_PITCH + d);
                qa[i][0] = v.x; qa[i][1] = v.y; qa[i][2] = v.z; qa[i][3] = v.w;
            }
#pragma unroll
            for (int j = 0; j < 4; j++) {
                float4 v = *(const float4*)(Ks + ((tx << 2) + j) * ATTN_PITCH + d);
                kb[j][0] = v.x; kb[j][1] = v.y; kb[j][2] = v.z; kb[j][3] = v.w;
            }
#pragma unroll
            for (int i = 0; i < 4; i++)
#pragma unroll
                for (int j = 0; j < 4; j++)
#pragma unroll
                    for (int dd = 0; dd < 4; dd++)
                        s[i][j] += qa[i][dd] * kb[j][dd];
        }

        if (kt == qt) {
#pragma unroll
            for (int i = 0; i < 4; i++)
#pragma unroll
                for (int j = 0; j < 4; j++)
                    if (((tx << 2) + j) > ((ty << 2) + i)) s[i][j] = -1e30f;
        }

#pragma unroll
        for (int i = 0; i < 4; i++) {
            float rm = fmaxf(fmaxf(s[i][0], s[i][1]), fmaxf(s[i][2], s[i][3]));
            rm = warp16_max(rm);
            float m_new = fmaxf(m_i[i], rm);
            float alpha = __expf(m_i[i] - m_new);
            float p[4], rs = 0.f;
#pragma unroll
            for (int j = 0; j < 4; j++) {
                p[j] = __expf(s[i][j] - m_new);
                rs  += p[j];
            }
            rs = warp16_sum(rs);
            l_i[i] = l_i[i] * alpha + rs;
            m_i[i] = m_new;
#pragma unroll
            for (int j = 0; j < 4; j++) {
                O[i][j] *= alpha;
                Ps[((ty << 2) + i) * ATTN_PITCH + (tx << 2) + j] = p[j];
            }
        }
        __syncthreads();

        for (int k0 = 0; k0 < 64; k0 += 4) {
            float pa[4][4], vb[4][4];
#pragma unroll
            for (int i = 0; i < 4; i++) {
                float4 v = *(const float4*)(Ps + ((ty << 2) + i) * ATTN_PITCH + k0);
                pa[i][0] = v.x; pa[i][1] = v.y; pa[i][2] = v.z; pa[i][3] = v.w;
            }
#pragma unroll
            for (int kk = 0; kk < 4; kk++) {
                float4 v = *(const float4*)(Vs + (k0 + kk) * ATTN_PITCH + (tx << 2));
                vb[kk][0] = v.x; vb[kk][1] = v.y; vb[kk][2] = v.z; vb[kk][3] = v.w;
            }
#pragma unroll
            for (int i = 0; i < 4; i++)
#pragma unroll
                for (int kk = 0; kk < 4; kk++)
#pragma unroll
                    for (int j = 0; j < 4; j++)
                        O[i][j] += pa[i][kk] * vb[kk][j];
        }
    }

#pragma unroll
    for (int i = 0; i < 4; i++) {
        float inv = 1.f / l_i[i];
        float4 o4;
        o4.x = O[i][0] * inv; o4.y = O[i][1] * inv;
        o4.z = O[i][2] * inv; o4.w = O[i][3] * inv;
        int r = qt * 64 + (ty << 2) + i;
        *(float4*)(g_ctx + (size_t)(b * SLEN + r) * DMODEL + h * DHEAD + (tx << 2)) = o4;
    }
}

// ---------------------------------------------------------------------------
extern "C" void kernel_launch(void* const* d_in, const int* in_sizes, int n_in,
                              void* d_out, int out_size)
{
    const float* x  = (const float*)d_in[0];
    const float* wq = (const float*)d_in[1];
    const float* wk = (const float*)d_in[2];
    const float* wv = (const float*)d_in[3];
    const float* wo = (const float*)d_in[4];
    const float* bo = (const float*)d_in[5];
    float* out = (float*)d_out;

    void *pq, *pk, *pv, *pctx;
    cudaGetSymbolAddress(&pq,   g_q);
    cudaGetSymbolAddress(&pk,   g_k);
    cudaGetSymbolAddress(&pv,   g_v);
    cudaGetSymbolAddress(&pctx, g_ctx);

    cudaFuncSetAttribute(attn_kernel,
                         cudaFuncAttributeMaxDynamicSharedMemorySize, ATTN_SMEM);
    cudaFuncSetAttribute(tf32_gemm_kernel,
                         cudaFuncAttributeMaxDynamicSharedMemorySize, GEMM_SMEM);

    dim3 gblk(256);
    dim3 ggrid(DMODEL / 128, MTOT / 128);   // (8, 32)

    tf32_gemm_kernel<<<ggrid, gblk, GEMM_SMEM>>>(x, wq, (float*)pq, MTOT,
                                                 DMODEL, DMODEL, 0.125f, nullptr);
    tf32_gemm_kernel<<<ggrid, gblk, GEMM_SMEM>>>(x, wk, (float*)pk, MTOT,
                                                 DMODEL, DMODEL, 1.0f, nullptr);
    tf32_gemm_kernel<<<ggrid, gblk, GEMM_SMEM>>>(x, wv, (float*)pv, MTOT,
                                                 DMODEL, DMODEL, 1.0f, nullptr);

    dim3 agrid(SLEN / 64, HEADS, BATCH);    // (32, 16, 2)
    attn_kernel<<<agrid, 256, ATTN_SMEM>>>();

    tf32_gemm_kernel<<<ggrid, gblk, GEMM_SMEM>>>((const float*)pctx, wo, out,
                                                 MTOT, DMODEL, DMODEL, 1.0f, bo);
}

// round 4
// speedup vs baseline: 2.7660x; 2.2110x over previous
#include <cuda_runtime.h>
#include <math.h>
#include <stdint.h>

#define BATCH  2
#define SLEN   2048
#define DMODEL 1024
#define HEADS  16
#define DHEAD  64
#define MTOT   (BATCH * SLEN)   // 4096

// ---------------- scratch (device globals; no allocation allowed) ----------
__device__ float g_q[MTOT * DMODEL];
__device__ float g_k[MTOT * DMODEL];
__device__ float g_v[MTOT * DMODEL];
__device__ float g_ctx[MTOT * DMODEL];

// ---------------- common tf32 helpers --------------------------------------
__device__ __forceinline__ uint32_t to_tf32(float x) {
    uint32_t r;
    asm("cvt.rna.tf32.f32 %0, %1;" : "=r"(r) : "f"(x));
    return r;
}

__device__ __forceinline__ void mma_tf32(float c[4], const uint32_t a[4],
                                         const uint32_t b[2]) {
    asm volatile(
        "mma.sync.aligned.m16n8k8.row.col.f32.tf32.tf32.f32 "
        "{%0,%1,%2,%3}, {%4,%5,%6,%7}, {%8,%9}, {%0,%1,%2,%3};"
        : "+f"(c[0]), "+f"(c[1]), "+f"(c[2]), "+f"(c[3])
        : "r"(a[0]), "r"(a[1]), "r"(a[2]), "r"(a[3]), "r"(b[0]), "r"(b[1]));
}

__device__ __forceinline__ float4 cvt4(float4 v) {
    float4 o;
    o.x = __uint_as_float(to_tf32(v.x));
    o.y = __uint_as_float(to_tf32(v.y));
    o.z = __uint_as_float(to_tf32(v.z));
    o.w = __uint_as_float(to_tf32(v.w));
    return o;
}

// ldmatrix.x4 on b16 8x8 tiles == one tf32 16x8 A-fragment (or two B-frags)
__device__ __forceinline__ void ldsm_x4(uint32_t r[4], const float* p) {
    uint32_t a = (uint32_t)__cvta_generic_to_shared(p);
    asm volatile(
        "ldmatrix.sync.aligned.m8n8.x4.shared.b16 {%0,%1,%2,%3}, [%4];"
        : "=r"(r[0]), "=r"(r[1]), "=r"(r[2]), "=r"(r[3]) : "r"(a));
}

// ===========================================================================
// tf32 tensor-core GEMM (unchanged from round 3, passing).
// ===========================================================================
#define GA_PITCH 36
#define GB_PITCH 132
#define GA_SIZE  (128 * GA_PITCH)
#define GB_SIZE  (32 * GB_PITCH)
#define GEMM_SMEM ((GA_SIZE + GB_SIZE) * 2 * (int)sizeof(float))

__global__ __launch_bounds__(256) void tf32_gemm_kernel(
    const float* __restrict__ A, const float* __restrict__ B,
    float* __restrict__ C, int M, int N, int K,
    float scale, const float* __restrict__ bias)
{
    extern __shared__ float sm[];
    float* AsBuf[2] = { sm, sm + GA_SIZE + GB_SIZE };
    float* BsBuf[2] = { sm + GA_SIZE, sm + 2 * GA_SIZE + GB_SIZE };

    const int t    = threadIdx.x;
    const int lane = t & 31;
    const int warp = t >> 5;
    const int m0   = blockIdx.y * 128;
    const int n0   = blockIdx.x * 128;
    const int wm   = (warp & 3) * 32;
    const int wn   = (warp >> 2) * 64;

    const int ar = t >> 3;
    const int ac = (t & 7) << 2;
    const int br = t >> 5;
    const int bc = (t & 31) << 2;

    const float* Ag = A + (size_t)m0 * K;
    const float* Bg = B + n0;

    float acc[2][8][4];
#pragma unroll
    for (int mi = 0; mi < 2; mi++)
#pragma unroll
        for (int ni = 0; ni < 8; ni++)
#pragma unroll
            for (int r = 0; r < 4; r++) acc[mi][ni][r] = 0.f;

    float4 aR[4], bR[4];
    const int nt = K / 32;

#pragma unroll
    for (int i = 0; i < 4; i++) {
        aR[i] = *(const float4*)(Ag + (size_t)(ar + i * 32) * K + ac);
        bR[i] = *(const float4*)(Bg + (size_t)(br + i * 8) * N + bc);
    }
#pragma unroll
    for (int i = 0; i < 4; i++) {
        *(float4*)(&AsBuf[0][(ar + i * 32) * GA_PITCH + ac]) = cvt4(aR[i]);
        *(float4*)(&BsBuf[0][(br + i * 8) * GB_PITCH + bc]) = cvt4(bR[i]);
    }
    __syncthreads();

    int cur = 0;
    for (int kt = 0; kt < nt; kt++) {
        if (kt + 1 < nt) {
            const int k0n = (kt + 1) * 32;
#pragma unroll
            for (int i = 0; i < 4; i++) {
                aR[i] = *(const float4*)(Ag + (size_t)(ar + i * 32) * K + k0n + ac);
                bR[i] = *(const float4*)(Bg + (size_t)(k0n + br + i * 8) * N + bc);
            }
        }

        const float* As = AsBuf[cur];
        const float* Bs = BsBuf[cur];
#pragma unroll
        for (int ks = 0; ks < 4; ks++) {
            const int k0 = ks * 8;
            uint32_t afr[2][4], bfr[8][2];
#pragma unroll
            for (int mi = 0; mi < 2; mi++) {
                int base = (wm + mi * 16 + (lane >> 2)) * GA_PITCH + k0 + (lane & 3);
                afr[mi][0] = __float_as_uint(As[base]);
                afr[mi][1] = __float_as_uint(As[base + 8 * GA_PITCH]);
                afr[mi][2] = __float_as_uint(As[base + 4]);
                afr[mi][3] = __float_as_uint(As[base + 8 * GA_PITCH + 4]);
            }
#pragma unroll
            for (int ni = 0; ni < 8; ni++) {
                int base = (k0 + (lane & 3)) * GB_PITCH + wn + ni * 8 + (lane >> 2);
                bfr[ni][0] = __float_as_uint(Bs[base]);
                bfr[ni][1] = __float_as_uint(Bs[base + 4 * GB_PITCH]);
            }
#pragma unroll
            for (int mi = 0; mi < 2; mi++)
#pragma unroll
                for (int ni = 0; ni < 8; ni++)
                    mma_tf32(acc[mi][ni], afr[mi], bfr[ni]);
        }

        if (kt + 1 < nt) {
            float* An = AsBuf[cur ^ 1];
            float* Bn = BsBuf[cur ^ 1];
#pragma unroll
            for (int i = 0; i < 4; i++) {
                *(float4*)(&An[(ar + i * 32) * GA_PITCH + ac]) = cvt4(aR[i]);
                *(float4*)(&Bn[(br + i * 8) * GB_PITCH + bc]) = cvt4(bR[i]);
            }
        }
        __syncthreads();
        cur ^= 1;
    }

#pragma unroll
    for (int mi = 0; mi < 2; mi++) {
        const int row0 = m0 + wm + mi * 16 + (lane >> 2);
#pragma unroll
        for (int ni = 0; ni < 8; ni++) {
            const int col = n0 + wn + ni * 8 + ((lane & 3) << 1);
            float b0 = 0.f, b1 = 0.f;
            if (bias) { b0 = bias[col]; b1 = bias[col + 1]; }
            float2 v0, v1;
            v0.x = acc[mi][ni][0] * scale + b0;
            v0.y = acc[mi][ni][1] * scale + b1;
            v1.x = acc[mi][ni][2] * scale + b0;
            v1.y = acc[mi][ni][3] * scale + b1;
            *(float2*)(C + (size_t)row0 * N + col) = v0;
            *(float2*)(C + (size_t)(row0 + 8) * N + col) = v1;
        }
    }
}

// ===========================================================================
// Causal flash attention on tf32 tensor cores.
// Block: 128 threads (4 warps), BQ=64, BK=64, Dh=64.
// Warp w owns q rows [w*16, w*16+16). Smem: QP (Q then reused for P), K, V,
// each 64 x AP floats (pitch 68 -> conflict-free ldmatrix row segments).
// Q fragments cached in registers for the whole kernel; O in mma accums.
// Score scale (0.125) was folded into the Q projection.
// ===========================================================================
#define AP 68
#define ATTN_SMEM (3 * 64 * AP * (int)sizeof(float))

__global__ __launch_bounds__(128) void attn_kernel()
{
    extern __shared__ float smf[];
    float* QPs = smf;               // Q tile, later reused as P tile
    float* Ks  = smf + 64 * AP;
    float* Vs  = smf + 2 * 64 * AP;

    const int qt   = blockIdx.x;
    const int h    = blockIdx.y;
    const int b    = blockIdx.z;
    const int t    = threadIdx.x;
    const int lane = t & 31;
    const int w    = t >> 5;

    const float* Qg = g_q + ((size_t)b * SLEN + qt * 64) * DMODEL + h * DHEAD;
    const float* Kg = g_k + (size_t)b * SLEN * DMODEL + h * DHEAD;
    const float* Vg = g_v + (size_t)b * SLEN * DMODEL + h * DHEAD;

    // ---- stage Q (tf32-rounded) into smem ----
#pragma unroll
    for (int i = 0; i < 8; i++) {
        int r = (t >> 4) + 8 * i;
        int c = (t & 15) << 2;
        *(float4*)(QPs + r * AP + c) =
            cvt4(*(const float4*)(Qg + (size_t)r * DMODEL + c));
    }
    __syncthreads();

    // ---- Q fragments (8 d-steps) into registers, then QPs is free for P ----
    uint32_t qa[8][4];
    {
        const float* base = QPs + (w * 16 + (lane & 15)) * AP + ((lane >> 4) << 2);
#pragma unroll
        for (int ds = 0; ds < 8; ds++)
            ldsm_x4(qa[ds], base + ds * 8);
    }

    float m0 = -1e30f, m1 = -1e30f, l0 = 0.f, l1 = 0.f;
    float O[8][4];
#pragma unroll
    for (int dn = 0; dn < 8; dn++)
#pragma unroll
        for (int r = 0; r < 4; r++) O[dn][r] = 0.f;

    const int r0 = lane >> 2;        // local row within warp block
    const int q2 = (lane & 3) << 1;  // col pair base within n-tile

    for (int kt = 0; kt <= qt; kt++) {
        __syncthreads();   // prev iter's Ks/Vs reads done (also covers Q frags)
        // ---- stage K, V (tf32) ----
#pragma unroll
        for (int i = 0; i < 8; i++) {
            int r = (t >> 4) + 8 * i;
            int c = (t & 15) << 2;
            size_t g = (size_t)(kt * 64 + r) * DMODEL + c;
            *(float4*)(Ks + r * AP + c) = cvt4(*(const float4*)(Kg + g));
            *(float4*)(Vs + r * AP + c) = cvt4(*(const float4*)(Vg + g));
        }
        __syncthreads();

        // ---- S = Q @ K^T ----
        float sacc[8][4];
#pragma unroll
        for (int n = 0; n < 8; n++)
#pragma unroll
            for (int r = 0; r < 4; r++) sacc[n][r] = 0.f;
        {
            const float* kbase = Ks + (((lane >> 4) << 3) + (lane & 7)) * AP
                                 + (((lane >> 3) & 1) << 2);
#pragma unroll
            for (int np = 0; np < 4; np++) {
#pragma unroll
                for (int ds = 0; ds < 8; ds++) {
                    uint32_t kb[4];
                    ldsm_x4(kb, kbase + np * 16 * AP + ds * 8);
                    mma_tf32(sacc[2 * np],     qa[ds], kb);
                    mma_tf32(sacc[2 * np + 1], qa[ds], kb + 2);
                }
            }
        }

        // ---- causal mask (diagonal tile only) ----
        if (kt == qt) {
            const int rg0 = w * 16 + r0;
            const int rg1 = rg0 + 8;
#pragma unroll
            for (int n = 0; n < 8; n++) {
                int c0 = n * 8 + q2;
                if (c0     > rg0) sacc[n][0] = -1e30f;
                if (c0 + 1 > rg0) sacc[n][1] = -1e30f;
                if (c0     > rg1) sacc[n][2] = -1e30f;
                if (c0 + 1 > rg1) sacc[n][3] = -1e30f;
            }
        }

        // ---- online softmax ----
        float mx0 = -1e30f, mx1 = -1e30f;
#pragma unroll
        for (int n = 0; n < 8; n++) {
            mx0 = fmaxf(mx0, fmaxf(sacc[n][0], sacc[n][1]));
            mx1 = fmaxf(mx1, fmaxf(sacc[n][2], sacc[n][3]));
        }
        mx0 = fmaxf(mx0, __shfl_xor_sync(0xffffffffu, mx0, 1));
        mx0 = fmaxf(mx0, __shfl_xor_sync(0xffffffffu, mx0, 2));
        mx1 = fmaxf(mx1, __shfl_xor_sync(0xffffffffu, mx1, 1));
        mx1 = fmaxf(mx1, __shfl_xor_sync(0xffffffffu, mx1, 2));

        const float nm0 = fmaxf(m0, mx0);
        const float nm1 = fmaxf(m1, mx1);
        const float a0  = __expf(m0 - nm0);
        const float a1  = __expf(m1 - nm1);
        float s0 = 0.f, s1 = 0.f;

        float* Prow0 = QPs + (w * 16 + r0) * AP + q2;
        float* Prow1 = Prow0 + 8 * AP;
#pragma unroll
        for (int n = 0; n < 8; n++) {
            float p00 = __expf(sacc[n][0] - nm0);
            float p01 = __expf(sacc[n][1] - nm0);
            float p10 = __expf(sacc[n][2] - nm1);
            float p11 = __expf(sacc[n][3] - nm1);
            s0 += p00 + p01;
            s1 += p10 + p11;
            float2 lo, hi;
            lo.x = __uint_as_float(to_tf32(p00));
            lo.y = __uint_as_float(to_tf32(p01));
            hi.x = __uint_as_float(to_tf32(p10));
            hi.y = __uint_as_float(to_tf32(p11));
            *(float2*)(Prow0 + n * 8) = lo;
            *(float2*)(Prow1 + n * 8) = hi;
        }
        s0 += __shfl_xor_sync(0xffffffffu, s0, 1);
        s0 += __shfl_xor_sync(0xffffffffu, s0, 2);
        s1 += __shfl_xor_sync(0xffffffffu, s1, 1);
        s1 += __shfl_xor_sync(0xffffffffu, s1, 2);

        l0 = l0 * a0 + s0;
        l1 = l1 * a1 + s1;
        m0 = nm0;
        m1 = nm1;
#pragma unroll
        for (int dn = 0; dn < 8; dn++) {
            O[dn][0] *= a0; O[dn][1] *= a0;
            O[dn][2] *= a1; O[dn][3] *= a1;
        }
        __syncwarp();   // P stores visible to this warp's ldmatrix reads

        // ---- O += P @ V ----
        {
            const float* pbase = QPs + (w * 16 + (lane & 15)) * AP
                                 + ((lane >> 4) << 2);
            const float* vb0base = Vs + (lane & 3) * AP + (lane >> 2);
#pragma unroll
            for (int ks = 0; ks < 8; ks++) {
                uint32_t pa[4];
                ldsm_x4(pa, pbase + ks * 8);
                const float* v0 = vb0base + ks * 8 * AP;
#pragma unroll
                for (int dn = 0; dn < 8; dn++) {
                    uint32_t vb[2];
                    vb[0] = __float_as_uint(v0[dn * 8]);
                    vb[1] = __float_as_uint(v0[4 * AP + dn * 8]);
                    mma_tf32(O[dn], pa, vb);
                }
            }
        }
    }

    // ---- finalize & write context ----
    const float inv0 = 1.f / l0;
    const float inv1 = 1.f / l1;
    const int rg0 = qt * 64 + w * 16 + r0;
    float* C0 = g_ctx + ((size_t)b * SLEN + rg0) * DMODEL + h * DHEAD + q2;
    float* C1 = C0 + 8 * DMODEL;
#pragma unroll
    for (int dn = 0; dn < 8; dn++) {
        float2 v0, v1;
        v0.x = O[dn][0] * inv0; v0.y = O[dn][1] * inv0;
        v1.x = O[dn][2] * inv1; v1.y = O[dn][3] * inv1;
        *(float2*)(C0 + dn * 8) = v0;
        *(float2*)(C1 + dn * 8) = v1;
    }
}

// ---------------------------------------------------------------------------
extern "C" void kernel_launch(void* const* d_in, const int* in_sizes, int n_in,
                              void* d_out, int out_size)
{
    const float* x  = (const float*)d_in[0];
    const float* wq = (const float*)d_in[1];
    const float* wk = (const float*)d_in[2];
    const float* wv = (const float*)d_in[3];
    const float* wo = (const float*)d_in[4];
    const float* bo = (const float*)d_in[5];
    float* out = (float*)d_out;

    void *pq, *pk, *pv, *pctx;
    cudaGetSymbolAddress(&pq,   g_q);
    cudaGetSymbolAddress(&pk,   g_k);
    cudaGetSymbolAddress(&pv,   g_v);
    cudaGetSymbolAddress(&pctx, g_ctx);

    cudaFuncSetAttribute(attn_kernel,
                         cudaFuncAttributeMaxDynamicSharedMemorySize, ATTN_SMEM);
    cudaFuncSetAttribute(tf32_gemm_kernel,
                         cudaFuncAttributeMaxDynamicSharedMemorySize, GEMM_SMEM);

    dim3 gblk(256);
    dim3 ggrid(DMODEL / 128, MTOT / 128);   // (8, 32)

    tf32_gemm_kernel<<<ggrid, gblk, GEMM_SMEM>>>(x, wq, (float*)pq, MTOT,
                                                 DMODEL, DMODEL, 0.125f, nullptr);
    tf32_gemm_kernel<<<ggrid, gblk, GEMM_SMEM>>>(x, wk, (float*)pk, MTOT,
                                                 DMODEL, DMODEL, 1.0f, nullptr);
    tf32_gemm_kernel<<<ggrid, gblk, GEMM_SMEM>>>(x, wv, (float*)pv, MTOT,
                                                 DMODEL, DMODEL, 1.0f, nullptr);

    dim3 agrid(SLEN / 64, HEADS, BATCH);    // (32, 16, 2)
    attn_kernel<<<agrid, 128, ATTN_SMEM>>>();

    tf32_gemm_kernel<<<ggrid, gblk, GEMM_SMEM>>>((const float*)pctx, wo, out,
                                                 MTOT, DMODEL, DMODEL, 1.0f, bo);
}

// round 6
// speedup vs baseline: 3.5003x; 1.2655x over previous
#include <cuda_runtime.h>
#include <math.h>
#include <stdint.h>

#define BATCH  2
#define SLEN   2048
#define DMODEL 1024
#define HEADS  16
#define DHEAD  64
#define MTOT   (BATCH * SLEN)   // 4096

// ---------------- scratch (device globals; no allocation allowed) ----------
__device__ float g_q[MTOT * DMODEL];
__device__ float g_k[MTOT * DMODEL];
__device__ float g_v[MTOT * DMODEL];
__device__ float g_ctx[MTOT * DMODEL];
__device__ float g_wT[4 * DMODEL * DMODEL];   // wq^T, wk^T, wv^T, wo^T (tf32)

// ---------------- common tf32 helpers --------------------------------------
__device__ __forceinline__ uint32_t to_tf32(float x) {
    uint32_t r;
    asm("cvt.rna.tf32.f32 %0, %1;" : "=r"(r) : "f"(x));
    return r;
}

__device__ __forceinline__ void mma_tf32(float c[4], const uint32_t a[4],
                                         const uint32_t b[2]) {
    asm volatile(
        "mma.sync.aligned.m16n8k8.row.col.f32.tf32.tf32.f32 "
        "{%0,%1,%2,%3}, {%4,%5,%6,%7}, {%8,%9}, {%0,%1,%2,%3};"
        : "+f"(c[0]), "+f"(c[1]), "+f"(c[2]), "+f"(c[3])
        : "r"(a[0]), "r"(a[1]), "r"(a[2]), "r"(a[3]), "r"(b[0]), "r"(b[1]));
}

__device__ __forceinline__ float4 cvt4(float4 v) {
    float4 o;
    o.x = __uint_as_float(to_tf32(v.x));
    o.y = __uint_as_float(to_tf32(v.y));
    o.z = __uint_as_float(to_tf32(v.z));
    o.w = __uint_as_float(to_tf32(v.w));
    return o;
}

__device__ __forceinline__ void ldsm_x4(uint32_t r[4], const float* p) {
    uint32_t a = (uint32_t)__cvta_generic_to_shared(p);
    asm volatile(
        "ldmatrix.sync.aligned.m8n8.x4.shared.b16 {%0,%1,%2,%3}, [%4];"
        : "=r"(r[0]), "=r"(r[1]), "=r"(r[2]), "=r"(r[3]) : "r"(a));
}

// ===========================================================================
// Weight transpose + tf32 rounding: g_wT[z] = W_z^T  (z = 0..3)
// ===========================================================================
__global__ __launch_bounds__(256) void transpose_cvt_kernel(
    const float* __restrict__ w0, const float* __restrict__ w1,
    const float* __restrict__ w2, const float* __restrict__ w3)
{
    __shared__ float tile[32][33];
    const int z = blockIdx.z;
    const float* src = (z == 0) ? w0 : (z == 1) ? w1 : (z == 2) ? w2 : w3;
    float* dst = g_wT + (size_t)z * DMODEL * DMODEL;

    const int tx = threadIdx.x, ty = threadIdx.y;
    const int k0 = blockIdx.y * 32, n0 = blockIdx.x * 32;

#pragma unroll
    for (int i = 0; i < 4; i++)
        tile[ty + 8 * i][tx] = src[(size_t)(k0 + ty + 8 * i) * DMODEL + n0 + tx];
    __syncthreads();
#pragma unroll
    for (int i = 0; i < 4; i++)
        dst[(size_t)(n0 + ty + 8 * i) * DMODEL + k0 + tx] =
            __uint_as_float(to_tf32(tile[tx][ty + 8 * i]));
}

// ===========================================================================
// tf32 GEMM with ldmatrix fragments: C[M,N] = A[M,K] @ BT[N,K]^T * scale (+bias)
// BT is pre-transposed AND pre-tf32-rounded. A rounded during staging.
// Tile 128x128x32, 256 thr, 8 warps (4M x 2N), warp tile 32x64.
// As, BsT: [128][32] pitch 36 (row stride 144B == 16B mod 128B -> ldsm clean).
// ===========================================================================
#define GP 36
#define GT_SIZE (128 * GP)
#define GEMM_SMEM (4 * GT_SIZE * (int)sizeof(float))   // 73728 B

__global__ __launch_bounds__(256) void tf32_gemm_kernel(
    const float* __restrict__ A, const float* __restrict__ BT,
    float* __restrict__ C, int M, int N, int K,
    float scale, const float* __restrict__ bias)
{
    extern __shared__ float sm[];
    float* AsBuf[2] = { sm, sm + 2 * GT_SIZE };
    float* BsBuf[2] = { sm + GT_SIZE, sm + 3 * GT_SIZE };

    const int t    = threadIdx.x;
    const int lane = t & 31;
    const int warp = t >> 5;
    const int m0   = blockIdx.y * 128;
    const int n0   = blockIdx.x * 128;
    const int wm   = (warp & 3) * 32;
    const int wn   = (warp >> 2) * 64;

    const int sr = t >> 3;          // staging row base (+32 per i)
    const int sc = (t & 7) << 2;    // staging col

    const float* Ag = A  + (size_t)m0 * K;
    const float* Bg = BT + (size_t)n0 * K;

    float acc[2][8][4];
#pragma unroll
    for (int mi = 0; mi < 2; mi++)
#pragma unroll
        for (int ni = 0; ni < 8; ni++)
#pragma unroll
            for (int r = 0; r < 4; r++) acc[mi][ni][r] = 0.f;

    float4 aR[4], bR[4];
    const int nt = K / 32;

#pragma unroll
    for (int i = 0; i < 4; i++) {
        aR[i] = *(const float4*)(Ag + (size_t)(sr + i * 32) * K + sc);
        bR[i] = *(const float4*)(Bg + (size_t)(sr + i * 32) * K + sc);
    }
#pragma unroll
    for (int i = 0; i < 4; i++) {
        *(float4*)(&AsBuf[0][(sr + i * 32) * GP + sc]) = cvt4(aR[i]);
        *(float4*)(&BsBuf[0][(sr + i * 32) * GP + sc]) = bR[i];
    }
    __syncthreads();

    int cur = 0;
    for (int kt = 0; kt < nt; kt++) {
        if (kt + 1 < nt) {
            const int k0n = (kt + 1) * 32;
#pragma unroll
            for (int i = 0; i < 4; i++) {
                aR[i] = *(const float4*)(Ag + (size_t)(sr + i * 32) * K + k0n + sc);
                bR[i] = *(const float4*)(Bg + (size_t)(sr + i * 32) * K + k0n + sc);
            }
        }

        const float* As = AsBuf[cur];
        const float* Bs = BsBuf[cur];
        // A-frag base (Q-style lane map), B-frag base (K-style lane map)
        const float* abase = As + (lane & 15) * GP + ((lane >> 4) << 2);
        const float* bbase = Bs + (((lane >> 4) << 3) + (lane & 7)) * GP
                             + (((lane >> 3) & 1) << 2);
#pragma unroll
        for (int ks = 0; ks < 4; ks++) {
            const int k0 = ks * 8;
            uint32_t afr[2][4];
#pragma unroll
            for (int mi = 0; mi < 2; mi++)
                ldsm_x4(afr[mi], abase + (wm + mi * 16) * GP + k0);
#pragma unroll
            for (int np = 0; np < 4; np++) {
                uint32_t bfr[4];
                ldsm_x4(bfr, bbase + (wn + np * 16) * GP + k0);
#pragma unroll
                for (int mi = 0; mi < 2; mi++) {
                    mma_tf32(acc[mi][2 * np],     afr[mi], bfr);
                    mma_tf32(acc[mi][2 * np + 1], afr[mi], bfr + 2);
                }
            }
        }

        if (kt + 1 < nt) {
            float* An = AsBuf[cur ^ 1];
            float* Bn = BsBuf[cur ^ 1];
#pragma unroll
            for (int i = 0; i < 4; i++) {
                *(float4*)(&An[(sr + i * 32) * GP + sc]) = cvt4(aR[i]);
                *(float4*)(&Bn[(sr + i * 32) * GP + sc]) = bR[i];
            }
        }
        __syncthreads();
        cur ^= 1;
    }

#pragma unroll
    for (int mi = 0; mi < 2; mi++) {
        const int row0 = m0 + wm + mi * 16 + (lane >> 2);
#pragma unroll
        for (int ni = 0; ni < 8; ni++) {
            const int col = n0 + wn + ni * 8 + ((lane & 3) << 1);
            float b0 = 0.f, b1 = 0.f;
            if (bias) { b0 = bias[col]; b1 = bias[col + 1]; }
            float2 v0, v1;
            v0.x = acc[mi][ni][0] * scale + b0;
            v0.y = acc[mi][ni][1] * scale + b1;
            v1.x = acc[mi][ni][2] * scale + b0;
            v1.y = acc[mi][ni][3] * scale + b1;
            *(float2*)(C + (size_t)row0 * N + col) = v0;
            *(float2*)(C + (size_t)(row0 + 8) * N + col) = v1;
        }
    }
}

// ===========================================================================
// Causal flash attention on tf32 tensor cores. BQ=128, BK=64, Dh=64.
// 256 threads (8 warps); warp w owns q rows [w*16, w*16+16).
// Smem: QP (Q, reused for P) 128 rows; K 64; V 64; pitch 68.
// ===========================================================================
#define AP 68
#define ATTN_SMEM ((128 + 64 + 64) * AP * (int)sizeof(float))

__global__ __launch_bounds__(256, 2) void attn_kernel()
{
    extern __shared__ float smf[];
    float* QPs = smf;                    // 128 x AP (Q then P)
    float* Ks  = smf + 128 * AP;         // 64 x AP
    float* Vs  = smf + 192 * AP;         // 64 x AP

    const int qt   = blockIdx.x;         // 0..15 (128-row q tiles)
    const int h    = blockIdx.y;
    const int b    = blockIdx.z;
    const int t    = threadIdx.x;
    const int lane = t & 31;
    const int w    = t >> 5;
    const int wbase = w * 16;

    const float* Qg = g_q + ((size_t)b * SLEN + qt * 128) * DMODEL + h * DHEAD;
    const float* Kg = g_k + (size_t)b * SLEN * DMODEL + h * DHEAD;
    const float* Vg = g_v + (size_t)b * SLEN * DMODEL + h * DHEAD;

    // ---- stage Q (tf32) ----
#pragma unroll
    for (int i = 0; i < 8; i++) {
        int r = (t >> 4) + 16 * i;
        int c = (t & 15) << 2;
        *(float4*)(QPs + r * AP + c) =
            cvt4(*(const float4*)(Qg + (size_t)r * DMODEL + c));
    }
    __syncthreads();

    // ---- Q fragments into registers ----
    uint32_t qa[8][4];
    {
        const float* base = QPs + (wbase + (lane & 15)) * AP + ((lane >> 4) << 2);
#pragma unroll
        for (int ds = 0; ds < 8; ds++)
            ldsm_x4(qa[ds], base + ds * 8);
    }

    float m0 = -1e30f, m1 = -1e30f, l0 = 0.f, l1 = 0.f;
    float O[8][4];
#pragma unroll
    for (int dn = 0; dn < 8; dn++)
#pragma unroll
        for (int r = 0; r < 4; r++) O[dn][r] = 0.f;

    const int r0 = lane >> 2;
    const int q2 = (lane & 3) << 1;
    const int ktmax = 2 * qt + 1;

    for (int kt = 0; kt <= ktmax; kt++) {
        __syncthreads();
        // ---- stage K, V (tf32) ----
#pragma unroll
        for (int i = 0; i < 4; i++) {
            int r = (t >> 4) + 16 * i;
            int c = (t & 15) << 2;
            size_t g = (size_t)(kt * 64 + r) * DMODEL + c;
            *(float4*)(Ks + r * AP + c) = cvt4(*(const float4*)(Kg + g));
            *(float4*)(Vs + r * AP + c) = cvt4(*(const float4*)(Vg + g));
        }
        __syncthreads();

        const int off = kt * 64 - qt * 128;   // tile col offset in local rows
        if (off <= wbase + 15) {              // warp has visible columns
            // ---- S = Q @ K^T ----
            float sacc[8][4];
#pragma unroll
            for (int n = 0; n < 8; n++)
#pragma unroll
                for (int r = 0; r < 4; r++) sacc[n][r] = 0.f;
            {
                const float* kbase = Ks + (((lane >> 4) << 3) + (lane & 7)) * AP
                                     + (((lane >> 3) & 1) << 2);
#pragma unroll
                for (int np = 0; np < 4; np++) {
#pragma unroll
                    for (int ds = 0; ds < 8; ds++) {
                        uint32_t kb[4];
                        ldsm_x4(kb, kbase + np * 16 * AP + ds * 8);
                        mma_tf32(sacc[2 * np],     qa[ds], kb);
                        mma_tf32(sacc[2 * np + 1], qa[ds], kb + 2);
                    }
                }
            }

            // ---- causal mask ----
            if (off + 63 > wbase) {
                const int rg0 = wbase + r0;
                const int rg1 = rg0 + 8;
#pragma unroll
                for (int n = 0; n < 8; n++) {
                    int c0 = off + n * 8 + q2;
                    if (c0     > rg0) sacc[n][0] = -1e30f;
                    if (c0 + 1 > rg0) sacc[n][1] = -1e30f;
                    if (c0     > rg1) sacc[n][2] = -1e30f;
                    if (c0 + 1 > rg1) sacc[n][3] = -1e30f;
                }
            }

            // ---- online softmax ----
            float mx0 = -1e30f, mx1 = -1e30f;
#pragma unroll
            for (int n = 0; n < 8; n++) {
                mx0 = fmaxf(mx0, fmaxf(sacc[n][0], sacc[n][1]));
                mx1 = fmaxf(mx1, fmaxf(sacc[n][2], sacc[n][3]));
            }
            mx0 = fmaxf(mx0, __shfl_xor_sync(0xffffffffu, mx0, 1));
            mx0 = fmaxf(mx0, __shfl_xor_sync(0xffffffffu, mx0, 2));
            mx1 = fmaxf(mx1, __shfl_xor_sync(0xffffffffu, mx1, 1));
            mx1 = fmaxf(mx1, __shfl_xor_sync(0xffffffffu, mx1, 2));

            const float nm0 = fmaxf(m0, mx0);
            const float nm1 = fmaxf(m1, mx1);
            const float a0  = __expf(m0 - nm0);
            const float a1  = __expf(m1 - nm1);
            float s0 = 0.f, s1 = 0.f;

            float* Prow0 = QPs + (wbase + r0) * AP + q2;
            float* Prow1 = Prow0 + 8 * AP;
#pragma unroll
            for (int n = 0; n < 8; n++) {
                float p00 = __expf(sacc[n][0] - nm0);
                float p01 = __expf(sacc[n][1] - nm0);
                float p10 = __expf(sacc[n][2] - nm1);
                float p11 = __expf(sacc[n][3] - nm1);
                s0 += p00 + p01;
                s1 += p10 + p11;
                float2 lo, hi;
                lo.x = __uint_as_float(to_tf32(p00));
                lo.y = __uint_as_float(to_tf32(p01));
                hi.x = __uint_as_float(to_tf32(p10));
                hi.y = __uint_as_float(to_tf32(p11));
                *(float2*)(Prow0 + n * 8) = lo;
                *(float2*)(Prow1 + n * 8) = hi;
            }
            s0 += __shfl_xor_sync(0xffffffffu, s0, 1);
            s0 += __shfl_xor_sync(0xffffffffu, s0, 2);
            s1 += __shfl_xor_sync(0xffffffffu, s1, 1);
            s1 += __shfl_xor_sync(0xffffffffu, s1, 2);

            l0 = l0 * a0 + s0;
            l1 = l1 * a1 + s1;
            m0 = nm0;
            m1 = nm1;
#pragma unroll
            for (int dn = 0; dn < 8; dn++) {
                O[dn][0] *= a0; O[dn][1] *= a0;
                O[dn][2] *= a1; O[dn][3] *= a1;
            }
            __syncwarp();

            // ---- O += P @ V ----
            {
                const float* pbase = QPs + (wbase + (lane & 15)) * AP
                                     + ((lane >> 4) << 2);
                const float* vb0base = Vs + (lane & 3) * AP + (lane >> 2);
#pragma unroll
                for (int ks = 0; ks < 8; ks++) {
                    uint32_t pa[4];
                    ldsm_x4(pa, pbase + ks * 8);
                    const float* v0 = vb0base + ks * 8 * AP;
#pragma unroll
                    for (int dn = 0; dn < 8; dn++) {
                        uint32_t vb[2];
                        vb[0] = __float_as_uint(v0[dn * 8]);
                        vb[1] = __float_as_uint(v0[4 * AP + dn * 8]);
                        mma_tf32(O[dn], pa, vb);
                    }
                }
            }
        }
    }

    // ---- finalize & write context ----
    const float inv0 = 1.f / l0;
    const float inv1 = 1.f / l1;
    const int rg0 = qt * 128 + wbase + r0;
    float* C0 = g_ctx + ((size_t)b * SLEN + rg0) * DMODEL + h * DHEAD + q2;
    float* C1 = C0 + 8 * DMODEL;
#pragma unroll
    for (int dn = 0; dn < 8; dn++) {
        float2 v0, v1;
        v0.x = O[dn][0] * inv0; v0.y = O[dn][1] * inv0;
        v1.x = O[dn][2] * inv1; v1.y = O[dn][3] * inv1;
        *(float2*)(C0 + dn * 8) = v0;
        *(float2*)(C1 + dn * 8) = v1;
    }
}

// ---------------------------------------------------------------------------
extern "C" void kernel_launch(void* const* d_in, const int* in_sizes, int n_in,
                              void* d_out, int out_size)
{
    const float* x  = (const float*)d_in[0];
    const float* wq = (const float*)d_in[1];
    const float* wk = (const float*)d_in[2];
    const float* wv = (const float*)d_in[3];
    const float* wo = (const float*)d_in[4];
    const float* bo = (const float*)d_in[5];
    float* out = (float*)d_out;

    void *pq, *pk, *pv, *pctx, *pwT;
    cudaGetSymbolAddress(&pq,   g_q);
    cudaGetSymbolAddress(&pk,   g_k);
    cudaGetSymbolAddress(&pv,   g_v);
    cudaGetSymbolAddress(&pctx, g_ctx);
    cudaGetSymbolAddress(&pwT,  g_wT);
    const float* wT = (const float*)pwT;

    cudaFuncSetAttribute(attn_kernel,
                         cudaFuncAttributeMaxDynamicSharedMemorySize, ATTN_SMEM);
    cudaFuncSetAttribute(tf32_gemm_kernel,
                         cudaFuncAttributeMaxDynamicSharedMemorySize, GEMM_SMEM);

    // weight transposes (+ tf32 rounding)
    transpose_cvt_kernel<<<dim3(32, 32, 4), dim3(32, 8)>>>(wq, wk, wv, wo);

    dim3 gblk(256);
    dim3 ggrid(DMODEL / 128, MTOT / 128);   // (8, 32)
    const size_t WSZ = (size_t)DMODEL * DMODEL;

    tf32_gemm_kernel<<<ggrid, gblk, GEMM_SMEM>>>(x, wT + 0 * WSZ, (float*)pq,
                                                 MTOT, DMODEL, DMODEL, 0.125f, nullptr);
    tf32_gemm_kernel<<<ggrid, gblk, GEMM_SMEM>>>(x, wT + 1 * WSZ, (float*)pk,
                                                 MTOT, DMODEL, DMODEL, 1.0f, nullptr);
    tf32_gemm_kernel<<<ggrid, gblk, GEMM_SMEM>>>(x, wT + 2 * WSZ, (float*)pv,
                                                 MTOT, DMODEL, DMODEL, 1.0f, nullptr);

    dim3 agrid(SLEN / 128, HEADS, BATCH);   // (16, 16, 2)
    attn_kernel<<<agrid, 256, ATTN_SMEM>>>();

    tf32_gemm_kernel<<<ggrid, gblk, GEMM_SMEM>>>((const float*)pctx, wT + 3 * WSZ,
                                                 out, MTOT, DMODEL, DMODEL, 1.0f, bo);
}

// round 7
// speedup vs baseline: 3.7479x; 1.0707x over previous
#include <cuda_runtime.h>
#include <math.h>
#include <stdint.h>

#define BATCH  2
#define SLEN   2048
#define DMODEL 1024
#define HEADS  16
#define DHEAD  64
#define MTOT   (BATCH * SLEN)   // 4096

// ---------------- scratch (device globals; no allocation allowed) ----------
__device__ float g_q[MTOT * DMODEL];
__device__ float g_k[MTOT * DMODEL];
__device__ float g_v[MTOT * DMODEL];
__device__ float g_ctx[MTOT * DMODEL];
__device__ float g_xc[MTOT * DMODEL];         // x pre-rounded to tf32
__device__ float g_wT[4 * DMODEL * DMODEL];   // wq^T, wk^T, wv^T, wo^T (tf32)

// ---------------- common helpers -------------------------------------------
__device__ __forceinline__ uint32_t to_tf32(float x) {
    uint32_t r;
    asm("cvt.rna.tf32.f32 %0, %1;" : "=r"(r) : "f"(x));
    return r;
}

__device__ __forceinline__ void mma_tf32(float c[4], const uint32_t a[4],
                                         const uint32_t b[2]) {
    asm volatile(
        "mma.sync.aligned.m16n8k8.row.col.f32.tf32.tf32.f32 "
        "{%0,%1,%2,%3}, {%4,%5,%6,%7}, {%8,%9}, {%0,%1,%2,%3};"
        : "+f"(c[0]), "+f"(c[1]), "+f"(c[2]), "+f"(c[3])
        : "r"(a[0]), "r"(a[1]), "r"(a[2]), "r"(a[3]), "r"(b[0]), "r"(b[1]));
}

__device__ __forceinline__ void ldsm_x4(uint32_t r[4], const float* p) {
    uint32_t a = (uint32_t)__cvta_generic_to_shared(p);
    asm volatile(
        "ldmatrix.sync.aligned.m8n8.x4.shared.b16 {%0,%1,%2,%3}, [%4];"
        : "=r"(r[0]), "=r"(r[1]), "=r"(r[2]), "=r"(r[3]) : "r"(a));
}

__device__ __forceinline__ void cp_async16(float* dst, const float* src) {
    uint32_t d = (uint32_t)__cvta_generic_to_shared(dst);
    asm volatile("cp.async.cg.shared.global [%0], [%1], 16;"
                 :: "r"(d), "l"(src));
}
__device__ __forceinline__ void cp_commit() {
    asm volatile("cp.async.commit_group;");
}
__device__ __forceinline__ void cp_wait1() {
    asm volatile("cp.async.wait_group 1;");
}
__device__ __forceinline__ void cp_wait0() {
    asm volatile("cp.async.wait_group 0;");
}

// ===========================================================================
// x -> tf32 pre-round (one pass)
// ===========================================================================
__global__ __launch_bounds__(256) void cvt_x_kernel(const float* __restrict__ x)
{
    const size_t i = ((size_t)blockIdx.x * 256 + threadIdx.x) * 4;
    float4 v = *(const float4*)(x + i);
    v.x = __uint_as_float(to_tf32(v.x));
    v.y = __uint_as_float(to_tf32(v.y));
    v.z = __uint_as_float(to_tf32(v.z));
    v.w = __uint_as_float(to_tf32(v.w));
    *(float4*)(g_xc + i) = v;
}

// ===========================================================================
// Weight transpose + tf32 rounding: g_wT[z] = W_z^T  (z = 0..3)
// ===========================================================================
__global__ __launch_bounds__(256) void transpose_cvt_kernel(
    const float* __restrict__ w0, const float* __restrict__ w1,
    const float* __restrict__ w2, const float* __restrict__ w3)
{
    __shared__ float tile[32][33];
    const int z = blockIdx.z;
    const float* src = (z == 0) ? w0 : (z == 1) ? w1 : (z == 2) ? w2 : w3;
    float* dst = g_wT + (size_t)z * DMODEL * DMODEL;

    const int tx = threadIdx.x, ty = threadIdx.y;
    const int k0 = blockIdx.y * 32, n0 = blockIdx.x * 32;

#pragma unroll
    for (int i = 0; i < 4; i++)
        tile[ty + 8 * i][tx] = src[(size_t)(k0 + ty + 8 * i) * DMODEL + n0 + tx];
    __syncthreads();
#pragma unroll
    for (int i = 0; i < 4; i++)
        dst[(size_t)(n0 + ty + 8 * i) * DMODEL + k0 + tx] =
            __uint_as_float(to_tf32(tile[tx][ty + 8 * i]));
}

// ===========================================================================
// tf32 GEMM, cp.async double-buffered: C = A @ BT^T * scale (+bias)
// A and BT are BOTH pre-tf32-rounded. Tile 128x128x32, 256 thr, 8 warps.
// roundOut: round results to tf32 on store (for q/k/v feeding attention).
// ===========================================================================
#define GP 36
#define GT_SIZE (128 * GP)
#define GEMM_SMEM (4 * GT_SIZE * (int)sizeof(float))   // 73728 B

__global__ __launch_bounds__(256, 2) void tf32_gemm_kernel(
    const float* __restrict__ A, const float* __restrict__ BT,
    float* __restrict__ C, int M, int N, int K,
    float scale, const float* __restrict__ bias, int roundOut)
{
    extern __shared__ float sm[];
    float* AsBuf[2] = { sm, sm + 2 * GT_SIZE };
    float* BsBuf[2] = { sm + GT_SIZE, sm + 3 * GT_SIZE };

    const int t    = threadIdx.x;
    const int lane = t & 31;
    const int warp = t >> 5;
    const int m0   = blockIdx.y * 128;
    const int n0   = blockIdx.x * 128;
    const int wm   = (warp & 3) * 32;
    const int wn   = (warp >> 2) * 64;

    const int sr = t >> 3;          // staging row base (+32 per i)
    const int sc = (t & 7) << 2;    // staging col

    const float* Ag = A  + (size_t)m0 * K + sc;
    const float* Bg = BT + (size_t)n0 * K + sc;

    float acc[2][8][4];
#pragma unroll
    for (int mi = 0; mi < 2; mi++)
#pragma unroll
        for (int ni = 0; ni < 8; ni++)
#pragma unroll
            for (int r = 0; r < 4; r++) acc[mi][ni][r] = 0.f;

    const int nt = K / 32;

    // stage tile kt into buffer buf
    auto stage = [&](int kt, int buf) {
        const int koff = kt * 32;
#pragma unroll
        for (int i = 0; i < 4; i++) {
            const int r = sr + i * 32;
            cp_async16(&AsBuf[buf][r * GP + sc], Ag + (size_t)r * K + koff);
            cp_async16(&BsBuf[buf][r * GP + sc], Bg + (size_t)r * K + koff);
        }
    };

    stage(0, 0);
    cp_commit();

    int cur = 0;
    for (int kt = 0; kt < nt; kt++) {
        if (kt + 1 < nt) { stage(kt + 1, cur ^ 1); cp_commit(); cp_wait1(); }
        else             { cp_wait0(); }
        __syncthreads();

        const float* As = AsBuf[cur];
        const float* Bs = BsBuf[cur];
        const float* abase = As + (lane & 15) * GP + ((lane >> 4) << 2);
        const float* bbase = Bs + (((lane >> 4) << 3) + (lane & 7)) * GP
                             + (((lane >> 3) & 1) << 2);
#pragma unroll
        for (int ks = 0; ks < 4; ks++) {
            const int k0 = ks * 8;
            uint32_t afr[2][4];
#pragma unroll
            for (int mi = 0; mi < 2; mi++)
                ldsm_x4(afr[mi], abase + (wm + mi * 16) * GP + k0);
#pragma unroll
            for (int np = 0; np < 4; np++) {
                uint32_t bfr[4];
                ldsm_x4(bfr, bbase + (wn + np * 16) * GP + k0);
#pragma unroll
                for (int mi = 0; mi < 2; mi++) {
                    mma_tf32(acc[mi][2 * np],     afr[mi], bfr);
                    mma_tf32(acc[mi][2 * np + 1], afr[mi], bfr + 2);
                }
            }
        }
        __syncthreads();   // all reads done before buffer reuse
        cur ^= 1;
    }

#pragma unroll
    for (int mi = 0; mi < 2; mi++) {
        const int row0 = m0 + wm + mi * 16 + (lane >> 2);
#pragma unroll
        for (int ni = 0; ni < 8; ni++) {
            const int col = n0 + wn + ni * 8 + ((lane & 3) << 1);
            float b0 = 0.f, b1 = 0.f;
            if (bias) { b0 = bias[col]; b1 = bias[col + 1]; }
            float2 v0, v1;
            v0.x = acc[mi][ni][0] * scale + b0;
            v0.y = acc[mi][ni][1] * scale + b1;
            v1.x = acc[mi][ni][2] * scale + b0;
            v1.y = acc[mi][ni][3] * scale + b1;
            if (roundOut) {
                v0.x = __uint_as_float(to_tf32(v0.x));
                v0.y = __uint_as_float(to_tf32(v0.y));
                v1.x = __uint_as_float(to_tf32(v1.x));
                v1.y = __uint_as_float(to_tf32(v1.y));
            }
            *(float2*)(C + (size_t)row0 * N + col) = v0;
            *(float2*)(C + (size_t)(row0 + 8) * N + col) = v1;
        }
    }
}

// ===========================================================================
// Causal flash attention, tf32 mma, cp.async double-buffered K/V.
// BQ=128, BK=64, 256 thr (8 warps); warp w owns q rows [w*16, w*16+16).
// Inputs q/k/v are pre-tf32-rounded by the projection GEMMs.
// Smem: QP (Q reused for P) 128 rows; K/V double buffers 4 x 64 rows; pitch 68.
// ===========================================================================
#define AP 68
#define ATTN_SMEM ((128 + 4 * 64) * AP * (int)sizeof(float))   // 104448 B

__global__ __launch_bounds__(256, 2) void attn_kernel()
{
    extern __shared__ float smf[];
    float* QPs = smf;                          // 128 x AP
    float* KsB[2] = { smf + 128 * AP, smf + 256 * AP };
    float* VsB[2] = { smf + 192 * AP, smf + 320 * AP };

    const int qt   = blockIdx.x;
    const int h    = blockIdx.y;
    const int b    = blockIdx.z;
    const int t    = threadIdx.x;
    const int lane = t & 31;
    const int w    = t >> 5;
    const int wbase = w * 16;

    const float* Qg = g_q + ((size_t)b * SLEN + qt * 128) * DMODEL + h * DHEAD;
    const float* Kg = g_k + (size_t)b * SLEN * DMODEL + h * DHEAD;
    const float* Vg = g_v + (size_t)b * SLEN * DMODEL + h * DHEAD;

    const int strow = t >> 4;            // 0..15
    const int stcol = (t & 15) << 2;     // 0..60

    // stage K/V tile kt into buffer buf (async)
    auto stageKV = [&](int kt, int buf) {
#pragma unroll
        for (int i = 0; i < 4; i++) {
            const int r = strow + 16 * i;
            const size_t g = (size_t)(kt * 64 + r) * DMODEL + stcol;
            cp_async16(KsB[buf] + r * AP + stcol, Kg + g);
            cp_async16(VsB[buf] + r * AP + stcol, Vg + g);
        }
    };

    // ---- stage Q (plain loads; already tf32) ----
#pragma unroll
    for (int i = 0; i < 8; i++) {
        const int r = strow + 16 * i;
        *(float4*)(QPs + r * AP + stcol) =
            *(const float4*)(Qg + (size_t)r * DMODEL + stcol);
    }

    stageKV(0, 0);
    cp_commit();
    __syncthreads();   // Q visible for fragment loads

    // ---- Q fragments into registers (QPs then free for P) ----
    uint32_t qa[8][4];
    {
        const float* base = QPs + (wbase + (lane & 15)) * AP + ((lane >> 4) << 2);
#pragma unroll
        for (int ds = 0; ds < 8; ds++)
            ldsm_x4(qa[ds], base + ds * 8);
    }

    float m0 = -1e30f, m1 = -1e30f, l0 = 0.f, l1 = 0.f;
    float O[8][4];
#pragma unroll
    for (int dn = 0; dn < 8; dn++)
#pragma unroll
        for (int r = 0; r < 4; r++) O[dn][r] = 0.f;

    const int r0 = lane >> 2;
    const int q2 = (lane & 3) << 1;
    const int ktmax = 2 * qt + 1;

    for (int kt = 0; kt <= ktmax; kt++) {
        if (kt < ktmax) { stageKV(kt + 1, (kt + 1) & 1); cp_commit(); cp_wait1(); }
        else            { cp_wait0(); }
        __syncthreads();

        const float* Ks = KsB[kt & 1];
        const float* Vs = VsB[kt & 1];
        const int off = kt * 64 - qt * 128;

        if (off <= wbase + 15) {
            // ---- S = Q @ K^T ----
            float sacc[8][4];
#pragma unroll
            for (int n = 0; n < 8; n++)
#pragma unroll
                for (int r = 0; r < 4; r++) sacc[n][r] = 0.f;
            {
                const float* kbase = Ks + (((lane >> 4) << 3) + (lane & 7)) * AP
                                     + (((lane >> 3) & 1) << 2);
#pragma unroll
                for (int np = 0; np < 4; np++) {
#pragma unroll
                    for (int ds = 0; ds < 8; ds++) {
                        uint32_t kb[4];
                        ldsm_x4(kb, kbase + np * 16 * AP + ds * 8);
                        mma_tf32(sacc[2 * np],     qa[ds], kb);
                        mma_tf32(sacc[2 * np + 1], qa[ds], kb + 2);
                    }
                }
            }

            // ---- causal mask ----
            if (off + 63 > wbase) {
                const int rg0 = wbase + r0;
                const int rg1 = rg0 + 8;
#pragma unroll
                for (int n = 0; n < 8; n++) {
                    int c0 = off + n * 8 + q2;
                    if (c0     > rg0) sacc[n][0] = -1e30f;
                    if (c0 + 1 > rg0) sacc[n][1] = -1e30f;
                    if (c0     > rg1) sacc[n][2] = -1e30f;
                    if (c0 + 1 > rg1) sacc[n][3] = -1e30f;
                }
            }

            // ---- online softmax ----
            float mx0 = -1e30f, mx1 = -1e30f;
#pragma unroll
            for (int n = 0; n < 8; n++) {
                mx0 = fmaxf(mx0, fmaxf(sacc[n][0], sacc[n][1]));
                mx1 = fmaxf(mx1, fmaxf(sacc[n][2], sacc[n][3]));
            }
            mx0 = fmaxf(mx0, __shfl_xor_sync(0xffffffffu, mx0, 1));
            mx0 = fmaxf(mx0, __shfl_xor_sync(0xffffffffu, mx0, 2));
            mx1 = fmaxf(mx1, __shfl_xor_sync(0xffffffffu, mx1, 1));
            mx1 = fmaxf(mx1, __shfl_xor_sync(0xffffffffu, mx1, 2));

            const float nm0 = fmaxf(m0, mx0);
            const float nm1 = fmaxf(m1, mx1);
            const float a0  = __expf(m0 - nm0);
            const float a1  = __expf(m1 - nm1);
            float s0 = 0.f, s1 = 0.f;

            float* Prow0 = QPs + (wbase + r0) * AP + q2;
            float* Prow1 = Prow0 + 8 * AP;
#pragma unroll
            for (int n = 0; n < 8; n++) {
                float p00 = __expf(sacc[n][0] - nm0);
                float p01 = __expf(sacc[n][1] - nm0);
                float p10 = __expf(sacc[n][2] - nm1);
                float p11 = __expf(sacc[n][3] - nm1);
                s0 += p00 + p01;
                s1 += p10 + p11;
                float2 lo, hi;
                lo.x = __uint_as_float(to_tf32(p00));
                lo.y = __uint_as_float(to_tf32(p01));
                hi.x = __uint_as_float(to_tf32(p10));
                hi.y = __uint_as_float(to_tf32(p11));
                *(float2*)(Prow0 + n * 8) = lo;
                *(float2*)(Prow1 + n * 8) = hi;
            }
            s0 += __shfl_xor_sync(0xffffffffu, s0, 1);
            s0 += __shfl_xor_sync(0xffffffffu, s0, 2);
            s1 += __shfl_xor_sync(0xffffffffu, s1, 1);
            s1 += __shfl_xor_sync(0xffffffffu, s1, 2);

            l0 = l0 * a0 + s0;
            l1 = l1 * a1 + s1;
            m0 = nm0;
            m1 = nm1;
#pragma unroll
            for (int dn = 0; dn < 8; dn++) {
                O[dn][0] *= a0; O[dn][1] *= a0;
                O[dn][2] *= a1; O[dn][3] *= a1;
            }
            __syncwarp();

            // ---- O += P @ V ----
            {
                const float* pbase = QPs + (wbase + (lane & 15)) * AP
                                     + ((lane >> 4) << 2);
                const float* vb0base = Vs + (lane & 3) * AP + (lane >> 2);
#pragma unroll
                for (int ks = 0; ks < 8; ks++) {
                    uint32_t pa[4];
                    ldsm_x4(pa, pbase + ks * 8);
                    const float* v0 = vb0base + ks * 8 * AP;
#pragma unroll
                    for (int dn = 0; dn < 8; dn++) {
                        uint32_t vb[2];
                        vb[0] = __float_as_uint(v0[dn * 8]);
                        vb[1] = __float_as_uint(v0[4 * AP + dn * 8]);
                        mma_tf32(O[dn], pa, vb);
                    }
                }
            }
        }
        __syncthreads();   // buffer reads done before overwrite next iter
    }

    // ---- finalize & write context (tf32-rounded for the wo GEMM) ----
    const float inv0 = 1.f / l0;
    const float inv1 = 1.f / l1;
    const int rg0 = qt * 128 + wbase + r0;
    float* C0 = g_ctx + ((size_t)b * SLEN + rg0) * DMODEL + h * DHEAD + q2;
    float* C1 = C0 + 8 * DMODEL;
#pragma unroll
    for (int dn = 0; dn < 8; dn++) {
        float2 v0, v1;
        v0.x = __uint_as_float(to_tf32(O[dn][0] * inv0));
        v0.y = __uint_as_float(to_tf32(O[dn][1] * inv0));
        v1.x = __uint_as_float(to_tf32(O[dn][2] * inv1));
        v1.y = __uint_as_float(to_tf32(O[dn][3] * inv1));
        *(float2*)(C0 + dn * 8) = v0;
        *(float2*)(C1 + dn * 8) = v1;
    }
}

// ---------------------------------------------------------------------------
extern "C" void kernel_launch(void* const* d_in, const int* in_sizes, int n_in,
                              void* d_out, int out_size)
{
    const float* x  = (const float*)d_in[0];
    const float* wq = (const float*)d_in[1];
    const float* wk = (const float*)d_in[2];
    const float* wv = (const float*)d_in[3];
    const float* wo = (const float*)d_in[4];
    const float* bo = (const float*)d_in[5];
    float* out = (float*)d_out;

    void *pq, *pk, *pv, *pctx, *pwT, *pxc;
    cudaGetSymbolAddress(&pq,   g_q);
    cudaGetSymbolAddress(&pk,   g_k);
    cudaGetSymbolAddress(&pv,   g_v);
    cudaGetSymbolAddress(&pctx, g_ctx);
    cudaGetSymbolAddress(&pwT,  g_wT);
    cudaGetSymbolAddress(&pxc,  g_xc);
    const float* wT = (const float*)pwT;
    const float* xc = (const float*)pxc;

    cudaFuncSetAttribute(attn_kernel,
                         cudaFuncAttributeMaxDynamicSharedMemorySize, ATTN_SMEM);
    cudaFuncSetAttribute(tf32_gemm_kernel,
                         cudaFuncAttributeMaxDynamicSharedMemorySize, GEMM_SMEM);

    // input pre-rounding passes
    transpose_cvt_kernel<<<dim3(32, 32, 4), dim3(32, 8)>>>(wq, wk, wv, wo);
    cvt_x_kernel<<<(MTOT * DMODEL) / (256 * 4), 256>>>(x);

    dim3 gblk(256);
    dim3 ggrid(DMODEL / 128, MTOT / 128);   // (8, 32)
    const size_t WSZ = (size_t)DMODEL * DMODEL;

    tf32_gemm_kernel<<<ggrid, gblk, GEMM_SMEM>>>(xc, wT + 0 * WSZ, (float*)pq,
                                                 MTOT, DMODEL, DMODEL, 0.125f,
                                                 nullptr, 1);
    tf32_gemm_kernel<<<ggrid, gblk, GEMM_SMEM>>>(xc, wT + 1 * WSZ, (float*)pk,
                                                 MTOT, DMODEL, DMODEL, 1.0f,
                                                 nullptr, 1);
    tf32_gemm_kernel<<<ggrid, gblk, GEMM_SMEM>>>(xc, wT + 2 * WSZ, (float*)pv,
                                                 MTOT, DMODEL, DMODEL, 1.0f,
                                                 nullptr, 1);

    dim3 agrid(SLEN / 128, HEADS, BATCH);   // (16, 16, 2)
    attn_kernel<<<agrid, 256, ATTN_SMEM>>>();

    tf32_gemm_kernel<<<ggrid, gblk, GEMM_SMEM>>>((const float*)pctx, wT + 3 * WSZ,
                                                 out, MTOT, DMODEL, DMODEL, 1.0f,
                                                 bo, 0);
}

// round 10
// speedup vs baseline: 3.9100x; 1.0433x over previous
#include <cuda_runtime.h>
#include <math.h>
#include <stdint.h>

#define BATCH  2
#define SLEN   2048
#define DMODEL 1024
#define HEADS  16
#define DHEAD  64
#define MTOT   (BATCH * SLEN)   // 4096

// ---------------- scratch (device globals; no allocation allowed) ----------
__device__ float g_q[MTOT * DMODEL];
__device__ float g_k[MTOT * DMODEL];
__device__ float g_v[MTOT * DMODEL];
__device__ float g_ctx[MTOT * DMODEL];
__device__ float g_xc[MTOT * DMODEL];         // x pre-rounded to tf32
__device__ float g_wT[4 * DMODEL * DMODEL];   // wq^T, wk^T, wv^T, wo^T (tf32)

// ---------------- helpers ---------------------------------------------------
__device__ __forceinline__ uint32_t to_tf32(float x) {
    uint32_t r;
    asm("cvt.rna.tf32.f32 %0, %1;" : "=r"(r) : "f"(x));
    return r;
}
__device__ __forceinline__ void mma_tf32(float c[4], const uint32_t a[4],
                                         const uint32_t b[2]) {
    asm volatile(
        "mma.sync.aligned.m16n8k8.row.col.f32.tf32.tf32.f32 "
        "{%0,%1,%2,%3}, {%4,%5,%6,%7}, {%8,%9}, {%0,%1,%2,%3};"
        : "+f"(c[0]), "+f"(c[1]), "+f"(c[2]), "+f"(c[3])
        : "r"(a[0]), "r"(a[1]), "r"(a[2]), "r"(a[3]), "r"(b[0]), "r"(b[1]));
}
__device__ __forceinline__ void ldsm_x4(uint32_t r[4], const void* p) {
    uint32_t a = (uint32_t)__cvta_generic_to_shared(p);
    asm volatile(
        "ldmatrix.sync.aligned.m8n8.x4.shared.b16 {%0,%1,%2,%3}, [%4];"
        : "=r"(r[0]), "=r"(r[1]), "=r"(r[2]), "=r"(r[3]) : "r"(a));
}
__device__ __forceinline__ void cp_async16(void* dst, const void* src) {
    uint32_t d = (uint32_t)__cvta_generic_to_shared(dst);
    asm volatile("cp.async.cg.shared.global [%0], [%1], 16;" :: "r"(d), "l"(src));
}
__device__ __forceinline__ void cp_commit() { asm volatile("cp.async.commit_group;"); }
__device__ __forceinline__ void cp_wait1()  { asm volatile("cp.async.wait_group 1;"); }
__device__ __forceinline__ void cp_wait0()  { asm volatile("cp.async.wait_group 0;"); }

// ===========================================================================
// prep kernels
// ===========================================================================
__global__ __launch_bounds__(256) void cvt_x_kernel(const float* __restrict__ x)
{
    const size_t i = ((size_t)blockIdx.x * 256 + threadIdx.x) * 4;
    float4 v = *(const float4*)(x + i);
    v.x = __uint_as_float(to_tf32(v.x));
    v.y = __uint_as_float(to_tf32(v.y));
    v.z = __uint_as_float(to_tf32(v.z));
    v.w = __uint_as_float(to_tf32(v.w));
    *(float4*)(g_xc + i) = v;
}

__global__ __launch_bounds__(256) void transpose_cvt_kernel(
    const float* __restrict__ w0, const float* __restrict__ w1,
    const float* __restrict__ w2, const float* __restrict__ w3)
{
    __shared__ float tile[32][33];
    const int z = blockIdx.z;
    const float* src = (z == 0) ? w0 : (z == 1) ? w1 : (z == 2) ? w2 : w3;
    float* dst = g_wT + (size_t)z * DMODEL * DMODEL;

    const int tx = threadIdx.x, ty = threadIdx.y;
    const int k0 = blockIdx.y * 32, n0 = blockIdx.x * 32;

#pragma unroll
    for (int i = 0; i < 4; i++)
        tile[ty + 8 * i][tx] = src[(size_t)(k0 + ty + 8 * i) * DMODEL + n0 + tx];
    __syncthreads();
#pragma unroll
    for (int i = 0; i < 4; i++)
        dst[(size_t)(n0 + ty + 8 * i) * DMODEL + k0 + tx] =
            __uint_as_float(to_tf32(tile[tx][ty + 8 * i]));
}

// ===========================================================================
// tf32 GEMM, 3-stage cp.async ring, ONE barrier per k-tile.
// phase 0: QKV fused (blockIdx.z selects weight/output); phase 1: out proj.
// q/k/v outputs tf32-rounded fp32 (feed attention); out proj plain fp32+bias.
// ===========================================================================
#define GP 36
#define GT_SIZE (128 * GP)
#define GEMM_SMEM (6 * GT_SIZE * (int)sizeof(float))   // 110592 B

__global__ __launch_bounds__(256, 2) void gemm_kernel(
    const float* __restrict__ A, const float* __restrict__ wTbase,
    float* __restrict__ outQ, float* __restrict__ outK,
    float* __restrict__ outV, float* __restrict__ outO,
    const float* __restrict__ bias, int phase)
{
    extern __shared__ float sm[];
    float* Ab[3] = { sm,           sm + 2*GT_SIZE, sm + 4*GT_SIZE };
    float* Bb[3] = { sm + GT_SIZE, sm + 3*GT_SIZE, sm + 5*GT_SIZE };

    const int z = blockIdx.z;
    const size_t WSZ = (size_t)DMODEL * DMODEL;
    const float* BT;
    float scale = 1.f;
    int roundOut;
    float* C;
    if (phase == 0) {
        BT = wTbase + (size_t)z * WSZ;
        roundOut = 1;
        if (z == 0)      { C = outQ; scale = 0.125f; }
        else if (z == 1) { C = outK; }
        else             { C = outV; }
    } else {
        BT = wTbase + 3 * WSZ;
        C = outO; roundOut = 0;
    }

    const int t    = threadIdx.x;
    const int lane = t & 31;
    const int warp = t >> 5;
    const int m0   = blockIdx.y * 128;
    const int n0   = blockIdx.x * 128;
    const int wm   = (warp & 3) * 32;
    const int wn   = (warp >> 2) * 64;
    const int N = DMODEL, K = DMODEL;

    const int sr = t >> 3;
    const int sc = (t & 7) << 2;

    const float* Ag = A  + (size_t)m0 * K + sc;
    const float* Bg = BT + (size_t)n0 * K + sc;

    float acc[2][8][4];
#pragma unroll
    for (int mi = 0; mi < 2; mi++)
#pragma unroll
        for (int ni = 0; ni < 8; ni++)
#pragma unroll
            for (int r = 0; r < 4; r++) acc[mi][ni][r] = 0.f;

    const int nt = K / 32;

    auto stage = [&](int kt, int buf) {
        const int koff = kt * 32;
#pragma unroll
        for (int i = 0; i < 4; i++) {
            const int r = sr + i * 32;
            cp_async16(&Ab[buf][r * GP + sc], Ag + (size_t)r * K + koff);
            cp_async16(&Bb[buf][r * GP + sc], Bg + (size_t)r * K + koff);
        }
    };

    stage(0, 0); cp_commit();
    stage(1, 1); cp_commit();

    for (int kt = 0; kt < nt; kt++) {
        if (kt < nt - 1) cp_wait1(); else cp_wait0();
        __syncthreads();

        const int cur = kt - (kt / 3) * 3;   // kt % 3
        const float* As = Ab[cur];
        const float* Bs = Bb[cur];
        const float* abase = As + (lane & 15) * GP + ((lane >> 4) << 2);
        const float* bbase = Bs + (((lane >> 4) << 3) + (lane & 7)) * GP
                             + (((lane >> 3) & 1) << 2);
#pragma unroll
        for (int ks = 0; ks < 4; ks++) {
            const int k0 = ks * 8;
            uint32_t afr[2][4];
#pragma unroll
            for (int mi = 0; mi < 2; mi++)
                ldsm_x4(afr[mi], abase + (wm + mi * 16) * GP + k0);
#pragma unroll
            for (int np = 0; np < 4; np++) {
                uint32_t bfr[4];
                ldsm_x4(bfr, bbase + (wn + np * 16) * GP + k0);
#pragma unroll
                for (int mi = 0; mi < 2; mi++) {
                    mma_tf32(acc[mi][2 * np],     afr[mi], bfr);
                    mma_tf32(acc[mi][2 * np + 1], afr[mi], bfr + 2);
                }
            }
        }

        if (kt + 2 < nt) {
            const int nb = (kt + 2) - ((kt + 2) / 3) * 3;
            stage(kt + 2, nb);
            cp_commit();
        }
    }

#pragma unroll
    for (int mi = 0; mi < 2; mi++) {
        const int row0 = m0 + wm + mi * 16 + (lane >> 2);
#pragma unroll
        for (int ni = 0; ni < 8; ni++) {
            const int col = n0 + wn + ni * 8 + ((lane & 3) << 1);
            float b0 = 0.f, b1 = 0.f;
            if (phase == 1 && bias) { b0 = bias[col]; b1 = bias[col + 1]; }
            float v00 = acc[mi][ni][0] * scale + b0;
            float v01 = acc[mi][ni][1] * scale + b1;
            float v10 = acc[mi][ni][2] * scale + b0;
            float v11 = acc[mi][ni][3] * scale + b1;
            if (roundOut) {
                v00 = __uint_as_float(to_tf32(v00));
                v01 = __uint_as_float(to_tf32(v01));
                v10 = __uint_as_float(to_tf32(v10));
                v11 = __uint_as_float(to_tf32(v11));
            }
            float2 a = {v00, v01}, b = {v10, v11};
            *(float2*)(C + (size_t)row0 * N + col) = a;
            *(float2*)(C + (size_t)(row0 + 8) * N + col) = b;
        }
    }
}

// ===========================================================================
// Causal flash attention, tf32 mma throughout (round-7 validated version).
// BQ=128, BK=64, 256 thr (8 warps); warp w owns q rows [w*16, w*16+16).
// Smem: QP (Q reused for P) 128 rows; K/V double buffers 4 x 64 rows; pitch 68.
// ===========================================================================
#define AP 68
#define ATTN_SMEM ((128 + 4 * 64) * AP * (int)sizeof(float))   // 104448 B

__global__ __launch_bounds__(256, 2) void attn_kernel()
{
    extern __shared__ float smf[];
    float* QPs = smf;                          // 128 x AP
    float* KsB[2] = { smf + 128 * AP, smf + 256 * AP };
    float* VsB[2] = { smf + 192 * AP, smf + 320 * AP };

    const int qt   = blockIdx.x;
    const int h    = blockIdx.y;
    const int b    = blockIdx.z;
    const int t    = threadIdx.x;
    const int lane = t & 31;
    const int w    = t >> 5;
    const int wbase = w * 16;

    const float* Qg = g_q + ((size_t)b * SLEN + qt * 128) * DMODEL + h * DHEAD;
    const float* Kg = g_k + (size_t)b * SLEN * DMODEL + h * DHEAD;
    const float* Vg = g_v + (size_t)b * SLEN * DMODEL + h * DHEAD;

    const int strow = t >> 4;            // 0..15
    const int stcol = (t & 15) << 2;     // 0..60

    auto stageKV = [&](int kt, int buf) {
#pragma unroll
        for (int i = 0; i < 4; i++) {
            const int r = strow + 16 * i;
            const size_t g = (size_t)(kt * 64 + r) * DMODEL + stcol;
            cp_async16(KsB[buf] + r * AP + stcol, Kg + g);
            cp_async16(VsB[buf] + r * AP + stcol, Vg + g);
        }
    };

    // ---- stage Q (plain loads; already tf32) ----
#pragma unroll
    for (int i = 0; i < 8; i++) {
        const int r = strow + 16 * i;
        *(float4*)(QPs + r * AP + stcol) =
            *(const float4*)(Qg + (size_t)r * DMODEL + stcol);
    }

    stageKV(0, 0);
    cp_commit();
    __syncthreads();   // Q visible for fragment loads

    // ---- Q fragments into registers (QPs then free for P) ----
    uint32_t qa[8][4];
    {
        const float* base = QPs + (wbase + (lane & 15)) * AP + ((lane >> 4) << 2);
#pragma unroll
        for (int ds = 0; ds < 8; ds++)
            ldsm_x4(qa[ds], base + ds * 8);
    }

    float m0 = -1e30f, m1 = -1e30f, l0 = 0.f, l1 = 0.f;
    float O[8][4];
#pragma unroll
    for (int dn = 0; dn < 8; dn++)
#pragma unroll
        for (int r = 0; r < 4; r++) O[dn][r] = 0.f;

    const int r0 = lane >> 2;
    const int q2 = (lane & 3) << 1;
    const int ktmax = 2 * qt + 1;

    for (int kt = 0; kt <= ktmax; kt++) {
        if (kt < ktmax) { stageKV(kt + 1, (kt + 1) & 1); cp_commit(); cp_wait1(); }
        else            { cp_wait0(); }
        __syncthreads();

        const float* Ks = KsB[kt & 1];
        const float* Vs = VsB[kt & 1];
        const int off = kt * 64 - qt * 128;

        if (off <= wbase + 15) {
            // ---- S = Q @ K^T ----
            float sacc[8][4];
#pragma unroll
            for (int n = 0; n < 8; n++)
#pragma unroll
                for (int r = 0; r < 4; r++) sacc[n][r] = 0.f;
            {
                const float* kbase = Ks + (((lane >> 4) << 3) + (lane & 7)) * AP
                                     + (((lane >> 3) & 1) << 2);
#pragma unroll
                for (int np = 0; np < 4; np++) {
#pragma unroll
                    for (int ds = 0; ds < 8; ds++) {
                        uint32_t kb[4];
                        ldsm_x4(kb, kbase + np * 16 * AP + ds * 8);
                        mma_tf32(sacc[2 * np],     qa[ds], kb);
                        mma_tf32(sacc[2 * np + 1], qa[ds], kb + 2);
                    }
                }
            }

            // ---- causal mask ----
            if (off + 63 > wbase) {
                const int rg0 = wbase + r0;
                const int rg1 = rg0 + 8;
#pragma unroll
                for (int n = 0; n < 8; n++) {
                    int c0 = off + n * 8 + q2;
                    if (c0     > rg0) sacc[n][0] = -1e30f;
                    if (c0 + 1 > rg0) sacc[n][1] = -1e30f;
                    if (c0     > rg1) sacc[n][2] = -1e30f;
                    if (c0 + 1 > rg1) sacc[n][3] = -1e30f;
                }
            }

            // ---- online softmax ----
            float mx0 = -1e30f, mx1 = -1e30f;
#pragma unroll
            for (int n = 0; n < 8; n++) {
                mx0 = fmaxf(mx0, fmaxf(sacc[n][0], sacc[n][1]));
                mx1 = fmaxf(mx1, fmaxf(sacc[n][2], sacc[n][3]));
            }
            mx0 = fmaxf(mx0, __shfl_xor_sync(0xffffffffu, mx0, 1));
            mx0 = fmaxf(mx0, __shfl_xor_sync(0xffffffffu, mx0, 2));
            mx1 = fmaxf(mx1, __shfl_xor_sync(0xffffffffu, mx1, 1));
            mx1 = fmaxf(mx1, __shfl_xor_sync(0xffffffffu, mx1, 2));

            const float nm0 = fmaxf(m0, mx0);
            const float nm1 = fmaxf(m1, mx1);
            const float a0  = __expf(m0 - nm0);
            const float a1  = __expf(m1 - nm1);
            float s0 = 0.f, s1 = 0.f;

            float* Prow0 = QPs + (wbase + r0) * AP + q2;
            float* Prow1 = Prow0 + 8 * AP;
#pragma unroll
            for (int n = 0; n < 8; n++) {
                float p00 = __expf(sacc[n][0] - nm0);
                float p01 = __expf(sacc[n][1] - nm0);
                float p10 = __expf(sacc[n][2] - nm1);
                float p11 = __expf(sacc[n][3] - nm1);
                s0 += p00 + p01;
                s1 += p10 + p11;
                float2 lo, hi;
                lo.x = __uint_as_float(to_tf32(p00));
                lo.y = __uint_as_float(to_tf32(p01));
                hi.x = __uint_as_float(to_tf32(p10));
                hi.y = __uint_as_float(to_tf32(p11));
                *(float2*)(Prow0 + n * 8) = lo;
                *(float2*)(Prow1 + n * 8) = hi;
            }
            s0 += __shfl_xor_sync(0xffffffffu, s0, 1);
            s0 += __shfl_xor_sync(0xffffffffu, s0, 2);
            s1 += __shfl_xor_sync(0xffffffffu, s1, 1);
            s1 += __shfl_xor_sync(0xffffffffu, s1, 2);

            l0 = l0 * a0 + s0;
            l1 = l1 * a1 + s1;
            m0 = nm0;
            m1 = nm1;
#pragma unroll
            for (int dn = 0; dn < 8; dn++) {
                O[dn][0] *= a0; O[dn][1] *= a0;
                O[dn][2] *= a1; O[dn][3] *= a1;
            }
            __syncwarp();

            // ---- O += P @ V ----
            {
                const float* pbase = QPs + (wbase + (lane & 15)) * AP
                                     + ((lane >> 4) << 2);
                const float* vb0base = Vs + (lane & 3) * AP + (lane >> 2);
#pragma unroll
                for (int ks = 0; ks < 8; ks++) {
                    uint32_t pa[4];
                    ldsm_x4(pa, pbase + ks * 8);
                    const float* v0 = vb0base + ks * 8 * AP;
#pragma unroll
                    for (int dn = 0; dn < 8; dn++) {
                        uint32_t vb[2];
                        vb[0] = __float_as_uint(v0[dn * 8]);
                        vb[1] = __float_as_uint(v0[4 * AP + dn * 8]);
                        mma_tf32(O[dn], pa, vb);
                    }
                }
            }
        }
        __syncthreads();   // buffer reads done before overwrite next iter
    }

    // ---- finalize & write context (tf32-rounded for the wo GEMM) ----
    const float inv0 = 1.f / l0;
    const float inv1 = 1.f / l1;
    const int rg0 = qt * 128 + wbase + r0;
    float* C0 = g_ctx + ((size_t)b * SLEN + rg0) * DMODEL + h * DHEAD + q2;
    float* C1 = C0 + 8 * DMODEL;
#pragma unroll
    for (int dn = 0; dn < 8; dn++) {
        float2 v0, v1;
        v0.x = __uint_as_float(to_tf32(O[dn][0] * inv0));
        v0.y = __uint_as_float(to_tf32(O[dn][1] * inv0));
        v1.x = __uint_as_float(to_tf32(O[dn][2] * inv1));
        v1.y = __uint_as_float(to_tf32(O[dn][3] * inv1));
        *(float2*)(C0 + dn * 8) = v0;
        *(float2*)(C1 + dn * 8) = v1;
    }
}

// ---------------------------------------------------------------------------
extern "C" void kernel_launch(void* const* d_in, const int* in_sizes, int n_in,
                              void* d_out, int out_size)
{
    const float* x  = (const float*)d_in[0];
    const float* wq = (const float*)d_in[1];
    const float* wk = (const float*)d_in[2];
    const float* wv = (const float*)d_in[3];
    const float* wo = (const float*)d_in[4];
    const float* bo = (const float*)d_in[5];
    float* out = (float*)d_out;

    void *pq, *pk, *pv, *pctx, *pwT, *pxc;
    cudaGetSymbolAddress(&pq,   g_q);
    cudaGetSymbolAddress(&pk,   g_k);
    cudaGetSymbolAddress(&pv,   g_v);
    cudaGetSymbolAddress(&pctx, g_ctx);
    cudaGetSymbolAddress(&pwT,  g_wT);
    cudaGetSymbolAddress(&pxc,  g_xc);

    cudaFuncSetAttribute(attn_kernel,
                         cudaFuncAttributeMaxDynamicSharedMemorySize, ATTN_SMEM);
    cudaFuncSetAttribute(gemm_kernel,
                         cudaFuncAttributeMaxDynamicSharedMemorySize, GEMM_SMEM);

    transpose_cvt_kernel<<<dim3(32, 32, 4), dim3(32, 8)>>>(wq, wk, wv, wo);
    cvt_x_kernel<<<(MTOT * DMODEL) / (256 * 4), 256>>>(x);

    dim3 gblk(256);

    // fused QKV projections (z selects weight/output)
    gemm_kernel<<<dim3(DMODEL / 128, MTOT / 128, 3), gblk, GEMM_SMEM>>>(
        (const float*)pxc, (const float*)pwT,
        (float*)pq, (float*)pk, (float*)pv, nullptr, nullptr, 0);

    // causal flash attention
    attn_kernel<<<dim3(SLEN / 128, HEADS, BATCH), 256, ATTN_SMEM>>>();

    // output projection + bias
    gemm_kernel<<<dim3(DMODEL / 128, MTOT / 128, 1), gblk, GEMM_SMEM>>>(
        (const float*)pctx, (const float*)pwT,
        nullptr, nullptr, nullptr, out, bo, 1);
}

// round 11
// speedup vs baseline: 4.4451x; 1.1369x over previous
#include <cuda_runtime.h>
#include <math.h>
#include <stdint.h>

#define BATCH  2
#define SLEN   2048
#define DMODEL 1024
#define HEADS  16
#define DHEAD  64
#define MTOT   (BATCH * SLEN)   // 4096

// ---------------- scratch (device globals; no allocation allowed) ----------
__device__ float g_q[MTOT * DMODEL];
__device__ float g_k[MTOT * DMODEL];
__device__ float g_v[MTOT * DMODEL];          // V TRANSPOSED: [b][h][d][s]
__device__ float g_ctx[MTOT * DMODEL];
__device__ float g_xc[MTOT * DMODEL];         // x pre-rounded to tf32
__device__ float g_wT[4 * DMODEL * DMODEL];   // wq^T, wk^T, wv^T, wo^T (tf32)

// ---------------- helpers ---------------------------------------------------
__device__ __forceinline__ uint32_t to_tf32(float x) {
    uint32_t r;
    asm("cvt.rna.tf32.f32 %0, %1;" : "=r"(r) : "f"(x));
    return r;
}
__device__ __forceinline__ void mma_tf32(float c[4], const uint32_t a[4],
                                         const uint32_t b[2]) {
    asm volatile(
        "mma.sync.aligned.m16n8k8.row.col.f32.tf32.tf32.f32 "
        "{%0,%1,%2,%3}, {%4,%5,%6,%7}, {%8,%9}, {%0,%1,%2,%3};"
        : "+f"(c[0]), "+f"(c[1]), "+f"(c[2]), "+f"(c[3])
        : "r"(a[0]), "r"(a[1]), "r"(a[2]), "r"(a[3]), "r"(b[0]), "r"(b[1]));
}
__device__ __forceinline__ void ldsm_x4(uint32_t r[4], const void* p) {
    uint32_t a = (uint32_t)__cvta_generic_to_shared(p);
    asm volatile(
        "ldmatrix.sync.aligned.m8n8.x4.shared.b16 {%0,%1,%2,%3}, [%4];"
        : "=r"(r[0]), "=r"(r[1]), "=r"(r[2]), "=r"(r[3]) : "r"(a));
}
__device__ __forceinline__ void cp_async16(void* dst, const void* src) {
    uint32_t d = (uint32_t)__cvta_generic_to_shared(dst);
    asm volatile("cp.async.cg.shared.global [%0], [%1], 16;" :: "r"(d), "l"(src));
}
__device__ __forceinline__ void cp_commit() { asm volatile("cp.async.commit_group;"); }
__device__ __forceinline__ void cp_wait1()  { asm volatile("cp.async.wait_group 1;"); }
__device__ __forceinline__ void cp_wait0()  { asm volatile("cp.async.wait_group 0;"); }

// ===========================================================================
// prep kernels
// ===========================================================================
__global__ __launch_bounds__(256) void cvt_x_kernel(const float* __restrict__ x)
{
    const size_t i = ((size_t)blockIdx.x * 256 + threadIdx.x) * 4;
    float4 v = *(const float4*)(x + i);
    v.x = __uint_as_float(to_tf32(v.x));
    v.y = __uint_as_float(to_tf32(v.y));
    v.z = __uint_as_float(to_tf32(v.z));
    v.w = __uint_as_float(to_tf32(v.w));
    *(float4*)(g_xc + i) = v;
}

__global__ __launch_bounds__(256) void transpose_cvt_kernel(
    const float* __restrict__ w0, const float* __restrict__ w1,
    const float* __restrict__ w2, const float* __restrict__ w3)
{
    __shared__ float tile[32][33];
    const int z = blockIdx.z;
    const float* src = (z == 0) ? w0 : (z == 1) ? w1 : (z == 2) ? w2 : w3;
    float* dst = g_wT + (size_t)z * DMODEL * DMODEL;

    const int tx = threadIdx.x, ty = threadIdx.y;
    const int k0 = blockIdx.y * 32, n0 = blockIdx.x * 32;

#pragma unroll
    for (int i = 0; i < 4; i++)
        tile[ty + 8 * i][tx] = src[(size_t)(k0 + ty + 8 * i) * DMODEL + n0 + tx];
    __syncthreads();
#pragma unroll
    for (int i = 0; i < 4; i++)
        dst[(size_t)(n0 + ty + 8 * i) * DMODEL + k0 + tx] =
            __uint_as_float(to_tf32(tile[tx][ty + 8 * i]));
}

// ===========================================================================
// tf32 GEMM, 3-stage cp.async ring, ONE barrier per k-tile.
// phase 0: QKV fused; z==2 (V) writes TRANSPOSED per-head [b][h][d][s].
// phase 1: output projection (+bias), fp32.
// ===========================================================================
#define GP 36
#define GT_SIZE (128 * GP)
#define GEMM_SMEM (6 * GT_SIZE * (int)sizeof(float))   // 110592 B

__global__ __launch_bounds__(256, 2) void gemm_kernel(
    const float* __restrict__ A, const float* __restrict__ wTbase,
    float* __restrict__ outQ, float* __restrict__ outK,
    float* __restrict__ outV, float* __restrict__ outO,
    const float* __restrict__ bias, int phase)
{
    extern __shared__ float sm[];
    float* Ab[3] = { sm,           sm + 2*GT_SIZE, sm + 4*GT_SIZE };
    float* Bb[3] = { sm + GT_SIZE, sm + 3*GT_SIZE, sm + 5*GT_SIZE };

    const int z = blockIdx.z;
    const size_t WSZ = (size_t)DMODEL * DMODEL;
    const float* BT;
    float scale = 1.f;
    int roundOut;
    float* C;
    if (phase == 0) {
        BT = wTbase + (size_t)z * WSZ;
        roundOut = 1;
        if (z == 0)      { C = outQ; scale = 0.125f; }
        else if (z == 1) { C = outK; }
        else             { C = outV; }
    } else {
        BT = wTbase + 3 * WSZ;
        C = outO; roundOut = 0;
    }

    const int t    = threadIdx.x;
    const int lane = t & 31;
    const int warp = t >> 5;
    const int m0   = blockIdx.y * 128;
    const int n0   = blockIdx.x * 128;
    const int wm   = (warp & 3) * 32;
    const int wn   = (warp >> 2) * 64;
    const int N = DMODEL, K = DMODEL;

    const int sr = t >> 3;
    const int sc = (t & 7) << 2;

    const float* Ag = A  + (size_t)m0 * K + sc;
    const float* Bg = BT + (size_t)n0 * K + sc;

    float acc[2][8][4];
#pragma unroll
    for (int mi = 0; mi < 2; mi++)
#pragma unroll
        for (int ni = 0; ni < 8; ni++)
#pragma unroll
            for (int r = 0; r < 4; r++) acc[mi][ni][r] = 0.f;

    const int nt = K / 32;

    auto stage = [&](int kt, int buf) {
        const int koff = kt * 32;
#pragma unroll
        for (int i = 0; i < 4; i++) {
            const int r = sr + i * 32;
            cp_async16(&Ab[buf][r * GP + sc], Ag + (size_t)r * K + koff);
            cp_async16(&Bb[buf][r * GP + sc], Bg + (size_t)r * K + koff);
        }
    };

    stage(0, 0); cp_commit();
    stage(1, 1); cp_commit();

    for (int kt = 0; kt < nt; kt++) {
        if (kt < nt - 1) cp_wait1(); else cp_wait0();
        __syncthreads();

        const int cur = kt - (kt / 3) * 3;   // kt % 3
        const float* As = Ab[cur];
        const float* Bs = Bb[cur];
        const float* abase = As + (lane & 15) * GP + ((lane >> 4) << 2);
        const float* bbase = Bs + (((lane >> 4) << 3) + (lane & 7)) * GP
                             + (((lane >> 3) & 1) << 2);
#pragma unroll
        for (int ks = 0; ks < 4; ks++) {
            const int k0 = ks * 8;
            uint32_t afr[2][4];
#pragma unroll
            for (int mi = 0; mi < 2; mi++)
                ldsm_x4(afr[mi], abase + (wm + mi * 16) * GP + k0);
#pragma unroll
            for (int np = 0; np < 4; np++) {
                uint32_t bfr[4];
                ldsm_x4(bfr, bbase + (wn + np * 16) * GP + k0);
#pragma unroll
                for (int mi = 0; mi < 2; mi++) {
                    mma_tf32(acc[mi][2 * np],     afr[mi], bfr);
                    mma_tf32(acc[mi][2 * np + 1], afr[mi], bfr + 2);
                }
            }
        }

        if (kt + 2 < nt) {
            const int nb = (kt + 2) - ((kt + 2) / 3) * 3;
            stage(kt + 2, nb);
            cp_commit();
        }
    }

    const bool vtrans = (phase == 0 && z == 2);
#pragma unroll
    for (int mi = 0; mi < 2; mi++) {
        const int row0 = m0 + wm + mi * 16 + (lane >> 2);
#pragma unroll
        for (int ni = 0; ni < 8; ni++) {
            const int col = n0 + wn + ni * 8 + ((lane & 3) << 1);
            float b0 = 0.f, b1 = 0.f;
            if (phase == 1 && bias) { b0 = bias[col]; b1 = bias[col + 1]; }
            float v00 = acc[mi][ni][0] * scale + b0;
            float v01 = acc[mi][ni][1] * scale + b1;
            float v10 = acc[mi][ni][2] * scale + b0;
            float v11 = acc[mi][ni][3] * scale + b1;
            if (roundOut) {
                v00 = __uint_as_float(to_tf32(v00));
                v01 = __uint_as_float(to_tf32(v01));
                v10 = __uint_as_float(to_tf32(v10));
                v11 = __uint_as_float(to_tf32(v11));
            }
            if (vtrans) {
                // (row,col) -> vT[b][h][d][s]; row = b*SLEN+s, col = h*64+d
                const int bb = row0 >> 11;          // / SLEN
                const int s  = row0 & (SLEN - 1);
                const int h  = col >> 6;
                const int d  = col & 63;
                float* vt = C + (((size_t)bb * HEADS + h) * DHEAD + d) * SLEN + s;
                vt[0]        = v00;   // (d,   s)
                vt[SLEN]     = v01;   // (d+1, s)
                vt[8]        = v10;   // (d,   s+8)
                vt[SLEN + 8] = v11;   // (d+1, s+8)
            } else {
                float2 a = {v00, v01}, b = {v10, v11};
                *(float2*)(C + (size_t)row0 * N + col) = a;
                *(float2*)(C + (size_t)(row0 + 8) * N + col) = b;
            }
        }
    }
}

// ===========================================================================
// Causal flash attention, tf32 mma. BQ=128, BK=64, 256 thr (8 warps).
// V is pre-transposed per head ([d][s]) -> PV B-fragments via ldmatrix,
// fully symmetric with QK. Heavy q-tiles launch first (qt reversed).
// Smem: QP (Q reused for P) 128 rows; K/VT double buffers; pitch 68.
// ===========================================================================
#define AP 68
#define ATTN_SMEM ((128 + 4 * 64) * AP * (int)sizeof(float))   // 104448 B

__global__ __launch_bounds__(256, 2) void attn_kernel()
{
    extern __shared__ float smf[];
    float* QPs = smf;                          // 128 x AP
    float* KsB[2]  = { smf + 128 * AP, smf + 256 * AP };
    float* VTsB[2] = { smf + 192 * AP, smf + 320 * AP };

    const int qt   = gridDim.x - 1 - blockIdx.x;   // heavy tiles first
    const int h    = blockIdx.y;
    const int b    = blockIdx.z;
    const int t    = threadIdx.x;
    const int lane = t & 31;
    const int w    = t >> 5;
    const int wbase = w * 16;

    const float* Qg  = g_q + ((size_t)b * SLEN + qt * 128) * DMODEL + h * DHEAD;
    const float* Kg  = g_k + (size_t)b * SLEN * DMODEL + h * DHEAD;
    const float* VTg = g_v + ((size_t)b * HEADS + h) * DHEAD * SLEN;  // [d][s]

    const int strow = t >> 4;            // 0..15
    const int stcol = (t & 15) << 2;     // 0..60
    const int vrow  = t >> 2;            // 0..63 (d)
    const int vcol4 = t & 3;             // float4 index base

    auto stageKV = [&](int kt, int buf) {
#pragma unroll
        for (int i = 0; i < 4; i++) {
            const int r = strow + 16 * i;
            cp_async16(KsB[buf] + r * AP + stcol,
                       Kg + (size_t)(kt * 64 + r) * DMODEL + stcol);
        }
#pragma unroll
        for (int i = 0; i < 4; i++) {
            const int c = (vcol4 + 4 * i) << 2;    // 0..60 floats
            cp_async16(VTsB[buf] + vrow * AP + c,
                       VTg + (size_t)vrow * SLEN + kt * 64 + c);
        }
    };

    // ---- stage Q (plain loads; already tf32) ----
#pragma unroll
    for (int i = 0; i < 8; i++) {
        const int r = strow + 16 * i;
        *(float4*)(QPs + r * AP + stcol) =
            *(const float4*)(Qg + (size_t)r * DMODEL + stcol);
    }

    stageKV(0, 0);
    cp_commit();
    __syncthreads();   // Q visible for fragment loads

    // ---- Q fragments into registers (QPs then free for P) ----
    uint32_t qa[8][4];
    {
        const float* base = QPs + (wbase + (lane & 15)) * AP + ((lane >> 4) << 2);
#pragma unroll
        for (int ds = 0; ds < 8; ds++)
            ldsm_x4(qa[ds], base + ds * 8);
    }

    float m0 = -1e30f, m1 = -1e30f, l0 = 0.f, l1 = 0.f;
    float O[8][4];
#pragma unroll
    for (int dn = 0; dn < 8; dn++)
#pragma unroll
        for (int r = 0; r < 4; r++) O[dn][r] = 0.f;

    const int r0 = lane >> 2;
    const int q2 = (lane & 3) << 1;
    const int ktmax = 2 * qt + 1;

    for (int kt = 0; kt <= ktmax; kt++) {
        if (kt < ktmax) { stageKV(kt + 1, (kt + 1) & 1); cp_commit(); cp_wait1(); }
        else            { cp_wait0(); }
        __syncthreads();

        const float* Ks  = KsB[kt & 1];
        const float* VTs = VTsB[kt & 1];
        const int off = kt * 64 - qt * 128;

        if (off <= wbase + 15) {
            // ---- S = Q @ K^T ----
            float sacc[8][4];
#pragma unroll
            for (int n = 0; n < 8; n++)
#pragma unroll
                for (int r = 0; r < 4; r++) sacc[n][r] = 0.f;
            {
                const float* kbase = Ks + (((lane >> 4) << 3) + (lane & 7)) * AP
                                     + (((lane >> 3) & 1) << 2);
#pragma unroll
                for (int np = 0; np < 4; np++) {
#pragma unroll
                    for (int ds = 0; ds < 8; ds++) {
                        uint32_t kb[4];
                        ldsm_x4(kb, kbase + np * 16 * AP + ds * 8);
                        mma_tf32(sacc[2 * np],     qa[ds], kb);
                        mma_tf32(sacc[2 * np + 1], qa[ds], kb + 2);
                    }
                }
            }

            // ---- causal mask ----
            if (off + 63 > wbase) {
                const int rg0 = wbase + r0;
                const int rg1 = rg0 + 8;
#pragma unroll
                for (int n = 0; n < 8; n++) {
                    int c0 = off + n * 8 + q2;
                    if (c0     > rg0) sacc[n][0] = -1e30f;
                    if (c0 + 1 > rg0) sacc[n][1] = -1e30f;
                    if (c0     > rg1) sacc[n][2] = -1e30f;
                    if (c0 + 1 > rg1) sacc[n][3] = -1e30f;
                }
            }

            // ---- online softmax ----
            float mx0 = -1e30f, mx1 = -1e30f;
#pragma unroll
            for (int n = 0; n < 8; n++) {
                mx0 = fmaxf(mx0, fmaxf(sacc[n][0], sacc[n][1]));
                mx1 = fmaxf(mx1, fmaxf(sacc[n][2], sacc[n][3]));
            }
            mx0 = fmaxf(mx0, __shfl_xor_sync(0xffffffffu, mx0, 1));
            mx0 = fmaxf(mx0, __shfl_xor_sync(0xffffffffu, mx0, 2));
            mx1 = fmaxf(mx1, __shfl_xor_sync(0xffffffffu, mx1, 1));
            mx1 = fmaxf(mx1, __shfl_xor_sync(0xffffffffu, mx1, 2));

            const float nm0 = fmaxf(m0, mx0);
            const float nm1 = fmaxf(m1, mx1);
            const float a0  = __expf(m0 - nm0);
            const float a1  = __expf(m1 - nm1);
            float s0 = 0.f, s1 = 0.f;

            float* Prow0 = QPs + (wbase + r0) * AP + q2;
            float* Prow1 = Prow0 + 8 * AP;
#pragma unroll
            for (int n = 0; n < 8; n++) {
                float p00 = __expf(sacc[n][0] - nm0);
                float p01 = __expf(sacc[n][1] - nm0);
                float p10 = __expf(sacc[n][2] - nm1);
                float p11 = __expf(sacc[n][3] - nm1);
                s0 += p00 + p01;
                s1 += p10 + p11;
                float2 lo, hi;
                lo.x = __uint_as_float(to_tf32(p00));
                lo.y = __uint_as_float(to_tf32(p01));
                hi.x = __uint_as_float(to_tf32(p10));
                hi.y = __uint_as_float(to_tf32(p11));
                *(float2*)(Prow0 + n * 8) = lo;
                *(float2*)(Prow1 + n * 8) = hi;
            }
            s0 += __shfl_xor_sync(0xffffffffu, s0, 1);
            s0 += __shfl_xor_sync(0xffffffffu, s0, 2);
            s1 += __shfl_xor_sync(0xffffffffu, s1, 1);
            s1 += __shfl_xor_sync(0xffffffffu, s1, 2);

            l0 = l0 * a0 + s0;
            l1 = l1 * a1 + s1;
            m0 = nm0;
            m1 = nm1;
#pragma unroll
            for (int dn = 0; dn < 8; dn++) {
                O[dn][0] *= a0; O[dn][1] *= a0;
                O[dn][2] *= a1; O[dn][3] *= a1;
            }
            __syncwarp();

            // ---- O += P @ V  (VT in smem -> K-style ldsm B-fragments) ----
            {
                const float* pbase = QPs + (wbase + (lane & 15)) * AP
                                     + ((lane >> 4) << 2);
                const float* vtbase = VTs + (((lane >> 4) << 3) + (lane & 7)) * AP
                                      + (((lane >> 3) & 1) << 2);
#pragma unroll
                for (int ks = 0; ks < 8; ks++) {
                    uint32_t pa[4];
                    ldsm_x4(pa, pbase + ks * 8);
#pragma unroll
                    for (int np = 0; np < 4; np++) {
                        uint32_t vb[4];
                        ldsm_x4(vb, vtbase + np * 16 * AP + ks * 8);
                        mma_tf32(O[2 * np],     pa, vb);
                        mma_tf32(O[2 * np + 1], pa, vb + 2);
                    }
                }
            }
        }
        __syncthreads();   // buffer reads done before overwrite next iter
    }

    // ---- finalize & write context (tf32-rounded for the wo GEMM) ----
    const float inv0 = 1.f / l0;
    const float inv1 = 1.f / l1;
    const int rg0 = qt * 128 + wbase + r0;
    float* C0 = g_ctx + ((size_t)b * SLEN + rg0) * DMODEL + h * DHEAD + q2;
    float* C1 = C0 + 8 * DMODEL;
#pragma unroll
    for (int dn = 0; dn < 8; dn++) {
        float2 v0, v1;
        v0.x = __uint_as_float(to_tf32(O[dn][0] * inv0));
        v0.y = __uint_as_float(to_tf32(O[dn][1] * inv0));
        v1.x = __uint_as_float(to_tf32(O[dn][2] * inv1));
        v1.y = __uint_as_float(to_tf32(O[dn][3] * inv1));
        *(float2*)(C0 + dn * 8) = v0;
        *(float2*)(C1 + dn * 8) = v1;
    }
}

// ---------------------------------------------------------------------------
extern "C" void kernel_launch(void* const* d_in, const int* in_sizes, int n_in,
                              void* d_out, int out_size)
{
    const float* x  = (const float*)d_in[0];
    const float* wq = (const float*)d_in[1];
    const float* wk = (const float*)d_in[2];
    const float* wv = (const float*)d_in[3];
    const float* wo = (const float*)d_in[4];
    const float* bo = (const float*)d_in[5];
    float* out = (float*)d_out;

    void *pq, *pk, *pv, *pctx, *pwT, *pxc;
    cudaGetSymbolAddress(&pq,   g_q);
    cudaGetSymbolAddress(&pk,   g_k);
    cudaGetSymbolAddress(&pv,   g_v);
    cudaGetSymbolAddress(&pctx, g_ctx);
    cudaGetSymbolAddress(&pwT,  g_wT);
    cudaGetSymbolAddress(&pxc,  g_xc);

    cudaFuncSetAttribute(attn_kernel,
                         cudaFuncAttributeMaxDynamicSharedMemorySize, ATTN_SMEM);
    cudaFuncSetAttribute(gemm_kernel,
                         cudaFuncAttributeMaxDynamicSharedMemorySize, GEMM_SMEM);

    transpose_cvt_kernel<<<dim3(32, 32, 4), dim3(32, 8)>>>(wq, wk, wv, wo);
    cvt_x_kernel<<<(MTOT * DMODEL) / (256 * 4), 256>>>(x);

    dim3 gblk(256);

    // fused QKV projections (z selects weight/output; V written transposed)
    gemm_kernel<<<dim3(DMODEL / 128, MTOT / 128, 3), gblk, GEMM_SMEM>>>(
        (const float*)pxc, (const float*)pwT,
        (float*)pq, (float*)pk, (float*)pv, nullptr, nullptr, 0);

    // causal flash attention
    attn_kernel<<<dim3(SLEN / 128, HEADS, BATCH), 256, ATTN_SMEM>>>();

    // output projection + bias
    gemm_kernel<<<dim3(DMODEL / 128, MTOT / 128, 1), gblk, GEMM_SMEM>>>(
        (const float*)pctx, (const float*)pwT,
        nullptr, nullptr, nullptr, out, bo, 1);
}